// round 7
// baseline (speedup 1.0000x reference)
#include <cuda_runtime.h>
#include <cuda_bf16.h>
#include <stdint.h>

#define B_ 32
#define N_ 4096
#define D_ 256
#define S_ 11
#define H_ 256
#define M_ 512

// ---------------- scratch (static device globals; no allocs) ----------------
__device__ __nv_bfloat16 g_ahi[(size_t)B_*N_*D_];
__device__ __nv_bfloat16 g_alo[(size_t)B_*N_*D_];
__device__ __nv_bfloat16 g_wthi[512*256];
__device__ __nv_bfloat16 g_wtlo[512*256];
__device__ float g_kf[(size_t)B_*N_*H_];
__device__ float g_vf[(size_t)B_*N_*H_];
__device__ float g_colsum[B_*S_];
__device__ float g_q[B_*S_*H_];
__device__ float g_updraw[B_*S_*H_];
__device__ float g_gx[B_*S_*3*H_];

// ---------------- helpers ----------------
__device__ __forceinline__ uint32_t smem_u32(const void* p) {
    uint32_t a;
    asm("{ .reg .u64 t; cvta.to.shared.u64 t, %1; cvt.u32.u64 %0, t; }" : "=r"(a) : "l"(p));
    return a;
}
__device__ __forceinline__ void ldsm_x4(uint32_t& r0, uint32_t& r1, uint32_t& r2, uint32_t& r3,
                                        uint32_t addr) {
    asm volatile("ldmatrix.sync.aligned.m8n8.x4.shared.b16 {%0,%1,%2,%3}, [%4];"
                 : "=r"(r0), "=r"(r1), "=r"(r2), "=r"(r3) : "r"(addr));
}
__device__ __forceinline__ void mma16816(float* d, const uint32_t* a, const uint32_t* b) {
    asm volatile("mma.sync.aligned.m16n8k16.row.col.f32.bf16.bf16.f32 "
                 "{%0,%1,%2,%3}, {%4,%5,%6,%7}, {%8,%9}, {%0,%1,%2,%3};"
                 : "+f"(d[0]), "+f"(d[1]), "+f"(d[2]), "+f"(d[3])
                 : "r"(a[0]), "r"(a[1]), "r"(a[2]), "r"(a[3]), "r"(b[0]), "r"(b[1]));
}
__device__ __forceinline__ void cp16(uint32_t saddr, const void* g) {
    asm volatile("cp.async.cg.shared.global [%0], [%1], 16;" :: "r"(saddr), "l"(g));
}
__device__ __forceinline__ void cp_commit() { asm volatile("cp.async.commit_group;" ::: "memory"); }
__device__ __forceinline__ void cp_wait1()  { asm volatile("cp.async.wait_group 1;" ::: "memory"); }
__device__ __forceinline__ void cp_wait0()  { asm volatile("cp.async.wait_group 0;" ::: "memory"); }

__device__ __forceinline__ void block_reduce2(float& s, float& q) {
    #pragma unroll
    for (int off = 16; off; off >>= 1) {
        s += __shfl_xor_sync(0xffffffffu, s, off);
        q += __shfl_xor_sync(0xffffffffu, q, off);
    }
    __shared__ float ss[8], sq[8];
    int w = threadIdx.x >> 5, l = threadIdx.x & 31;
    if (l == 0) { ss[w] = s; sq[w] = q; }
    __syncthreads();
    s = 0.f; q = 0.f;
    #pragma unroll
    for (int i = 0; i < 8; i++) { s += ss[i]; q += sq[i]; }
}

// ---------------- 1) k_q: init slots + zero accum + LN(slots) + q = LN@Wq*scale ----------------
__global__ void __launch_bounds__(256) k_q(const float* __restrict__ noise,
                                           const float* __restrict__ mu, const float* __restrict__ ls,
                                           const float* __restrict__ g, const float* __restrict__ o,
                                           const float* __restrict__ Wq, float* __restrict__ slots)
{
    __shared__ float lns[256];
    int r = blockIdx.x, tid = threadIdx.x;
    float val = mu[tid] + expf(ls[tid]) * noise[r * 256 + tid];
    slots[r * 256 + tid] = val;
    g_updraw[r * 256 + tid] = 0.f;
    if (tid == 0) g_colsum[r] = 0.f;

    float s_ = val, q_ = val * val;
    block_reduce2(s_, q_);
    float muv = s_ * (1.f / 256.f);
    float var = q_ * (1.f / 256.f) - muv * muv;
    float rs = rsqrtf(var + 1e-5f);
    lns[tid] = (val - muv) * rs * g[tid] + o[tid];
    __syncthreads();

    const float* wp = Wq + tid;
    float a0 = 0.f, a1 = 0.f, a2 = 0.f, a3 = 0.f;
    #pragma unroll 4
    for (int k = 0; k < 256; k += 4) {
        a0 = fmaf(lns[k],     wp[(size_t)k * 256],       a0);
        a1 = fmaf(lns[k + 1], wp[(size_t)(k + 1) * 256], a1);
        a2 = fmaf(lns[k + 2], wp[(size_t)(k + 2) * 256], a2);
        a3 = fmaf(lns[k + 3], wp[(size_t)(k + 3) * 256], a3);
    }
    g_q[r * 256 + tid] = ((a0 + a1) + (a2 + a3)) * 0.0625f;
}

// ---------------- 2) combined input-prep + weight-prep ----------------
__global__ void __launch_bounds__(256) k_prepall(const float* __restrict__ x,
                                                 const float* __restrict__ g,
                                                 const float* __restrict__ o,
                                                 const float* __restrict__ wk,
                                                 const float* __restrict__ wv)
{
    if (blockIdx.x >= 16384) {
        int idx = (blockIdx.x - 16384) * 256 + threadIdx.x;
        int j = idx >> 8;
        int k = idx & 255;
        float w = (j < 256) ? wk[k * 256 + j] : wv[k * 256 + (j - 256)];
        __nv_bfloat16 h = __float2bfloat16_rn(w);
        g_wthi[idx] = h;
        g_wtlo[idx] = __float2bfloat16_rn(w - __bfloat162float(h));
        return;
    }
    int wid = threadIdx.x >> 5, lane = threadIdx.x & 31;
    int row = blockIdx.x * 8 + wid;
    const float4* xp = (const float4*)&x[(size_t)row * 256 + lane * 8];
    float4 a = xp[0], b = xp[1];
    float s = a.x + a.y + a.z + a.w + b.x + b.y + b.z + b.w;
    float q = a.x*a.x + a.y*a.y + a.z*a.z + a.w*a.w
            + b.x*b.x + b.y*b.y + b.z*b.z + b.w*b.w;
    #pragma unroll
    for (int off = 16; off; off >>= 1) {
        s += __shfl_xor_sync(0xffffffffu, s, off);
        q += __shfl_xor_sync(0xffffffffu, q, off);
    }
    float mu = s * (1.f / 256.f);
    float var = q * (1.f / 256.f) - mu * mu;
    float rs = rsqrtf(var + 1e-5f);

    const float4* gp = (const float4*)&g[lane * 8];
    const float4* op = (const float4*)&o[lane * 8];
    float4 g0 = gp[0], g1 = gp[1], o0 = op[0], o1 = op[1];

    float v[8];
    v[0] = (a.x - mu) * rs * g0.x + o0.x;
    v[1] = (a.y - mu) * rs * g0.y + o0.y;
    v[2] = (a.z - mu) * rs * g0.z + o0.z;
    v[3] = (a.w - mu) * rs * g0.w + o0.w;
    v[4] = (b.x - mu) * rs * g1.x + o1.x;
    v[5] = (b.y - mu) * rs * g1.y + o1.y;
    v[6] = (b.z - mu) * rs * g1.z + o1.z;
    v[7] = (b.w - mu) * rs * g1.w + o1.w;

    float hf[8], lf[8];
    #pragma unroll
    for (int i = 0; i < 8; i++) {
        __nv_bfloat16 h = __float2bfloat16_rn(v[i]);
        hf[i] = __bfloat162float(h);
        lf[i] = v[i] - hf[i];
    }
    __nv_bfloat162 h01 = __floats2bfloat162_rn(hf[0], hf[1]);
    __nv_bfloat162 h23 = __floats2bfloat162_rn(hf[2], hf[3]);
    __nv_bfloat162 h45 = __floats2bfloat162_rn(hf[4], hf[5]);
    __nv_bfloat162 h67 = __floats2bfloat162_rn(hf[6], hf[7]);
    __nv_bfloat162 l01 = __floats2bfloat162_rn(lf[0], lf[1]);
    __nv_bfloat162 l23 = __floats2bfloat162_rn(lf[2], lf[3]);
    __nv_bfloat162 l45 = __floats2bfloat162_rn(lf[4], lf[5]);
    __nv_bfloat162 l67 = __floats2bfloat162_rn(lf[6], lf[7]);
    uint4 uh, ul;
    uh.x = *(uint32_t*)&h01; uh.y = *(uint32_t*)&h23; uh.z = *(uint32_t*)&h45; uh.w = *(uint32_t*)&h67;
    ul.x = *(uint32_t*)&l01; ul.y = *(uint32_t*)&l23; ul.z = *(uint32_t*)&l45; ul.w = *(uint32_t*)&l67;
    *(uint4*)&g_ahi[(size_t)row * 256 + lane * 8] = uh;
    *(uint4*)&g_alo[(size_t)row * 256 + lane * 8] = ul;
}

// ---------------- 3) mma.sync split-bf16 GEMM, 512 threads, 32x32 warp tiles ----------------
#define SM_AH 0
#define SM_AL 16384
#define SM_BH 32768
#define SM_BL 49152
#define STAGE_SZ 65536
#define SMEM_SZ (2 * STAGE_SZ)

__device__ __forceinline__ void mma_fill(uint32_t sb, int st, int rowbase, size_t jb, int kb, int tid) {
    uint32_t so = st * STAGE_SZ;
    #pragma unroll
    for (int i = 0; i < 2; i++) {
        int idx = tid + i * 512;
        int row = idx >> 3, c8 = idx & 7;
        uint32_t bo = row * 128 + c8 * 16;
        uint32_t sw = (bo ^ ((bo >> 3) & 0x70)) + so;
        size_t srcA = (size_t)(rowbase + row) * 256 + kb + c8 * 8;
        size_t srcB = jb + (size_t)row * 256 + kb + c8 * 8;
        cp16(sb + SM_AH + sw, &g_ahi[srcA]);
        cp16(sb + SM_AL + sw, &g_alo[srcA]);
        cp16(sb + SM_BH + sw, &g_wthi[srcB]);
        cp16(sb + SM_BL + sw, &g_wtlo[srcB]);
    }
    cp_commit();
}

__global__ void __launch_bounds__(512, 1) k_mma_kv()
{
    extern __shared__ __align__(1024) uint8_t smem[];
    uint32_t sbase = smem_u32(smem);
    int tid = threadIdx.x;
    int lane = tid & 31;
    int warp = tid >> 5;        // 0..15
    int wm = warp & 3;          // 4 M-blocks of 32
    int wn = warp >> 2;         // 4 N-blocks of 32

    int half = blockIdx.x >> 1;
    int ntile = blockIdx.x & 1;
    int rowbase = blockIdx.y * 128;
    size_t jb = ((size_t)half * 256 + ntile * 128) * 256;

    float acc[2][4][4];
    #pragma unroll
    for (int mf = 0; mf < 2; mf++)
        #pragma unroll
        for (int nf = 0; nf < 4; nf++)
            #pragma unroll
            for (int r = 0; r < 4; r++) acc[mf][nf][r] = 0.f;

    uint32_t lrow = ((lane >> 3) & 1) * 8 + (lane & 7);
    uint32_t lcol = ((lane >> 4) & 1) * 16;

    mma_fill(sbase, 0, rowbase, jb, 0, tid);
    mma_fill(sbase, 1, rowbase, jb, 64, tid);

    for (int ch = 0; ch < 4; ch++) {
        if (ch < 3) cp_wait1();
        else        cp_wait0();
        __syncthreads();
        uint32_t so = (ch & 1) * STAGE_SZ;

        #pragma unroll
        for (int ks = 0; ks < 4; ks++) {
            uint32_t cb = ks * 32 + lcol;
            uint32_t ah[2][4], al[2][4];
            #pragma unroll
            for (int mf = 0; mf < 2; mf++) {
                uint32_t r = wm * 32 + mf * 16 + lrow;
                uint32_t bo = r * 128 + cb;
                uint32_t sw = (bo ^ ((bo >> 3) & 0x70)) + so;
                ldsm_x4(ah[mf][0], ah[mf][1], ah[mf][2], ah[mf][3], sbase + SM_AH + sw);
                ldsm_x4(al[mf][0], al[mf][1], al[mf][2], al[mf][3], sbase + SM_AL + sw);
            }
            uint32_t bh[4][2], bl[4][2];
            #pragma unroll
            for (int g = 0; g < 2; g++) {
                uint32_t r = wn * 32 + g * 16 + lrow;
                uint32_t bo = r * 128 + cb;
                uint32_t sw = (bo ^ ((bo >> 3) & 0x70)) + so;
                uint32_t t0, t1, t2, t3;
                ldsm_x4(t0, t1, t2, t3, sbase + SM_BH + sw);
                bh[g * 2][0] = t0; bh[g * 2 + 1][0] = t1;
                bh[g * 2][1] = t2; bh[g * 2 + 1][1] = t3;
                ldsm_x4(t0, t1, t2, t3, sbase + SM_BL + sw);
                bl[g * 2][0] = t0; bl[g * 2 + 1][0] = t1;
                bl[g * 2][1] = t2; bl[g * 2 + 1][1] = t3;
            }
            #pragma unroll
            for (int mf = 0; mf < 2; mf++)
                #pragma unroll
                for (int nf = 0; nf < 4; nf++) {
                    mma16816(acc[mf][nf], ah[mf], bh[nf]);
                    mma16816(acc[mf][nf], ah[mf], bl[nf]);
                    mma16816(acc[mf][nf], al[mf], bh[nf]);
                }
        }
        __syncthreads();
        if (ch < 2) mma_fill(sbase, ch & 1, rowbase, jb, (ch + 2) * 64, tid);
    }

    float* outp = (half == 0) ? g_kf : g_vf;
    int r0 = rowbase + wm * 32 + (lane >> 2);
    int c0 = ntile * 128 + wn * 32 + (lane & 3) * 2;
    #pragma unroll
    for (int mf = 0; mf < 2; mf++)
        #pragma unroll
        for (int nf = 0; nf < 4; nf++) {
            float* d = acc[mf][nf];
            size_t base = (size_t)(r0 + mf * 16) * 256 + c0 + nf * 8;
            *(float2*)&outp[base] = make_float2(d[0], d[1]);
            *(float2*)&outp[base + 8 * 256] = make_float2(d[2], d[3]);
        }
}

// ---------------- 4) fused attention, double-buffered p, 1 sync per 64-row segment ----------------
__global__ void __launch_bounds__(256, 2) k_attn_upd()
{
    __shared__ __align__(16) float qs[11][256];
    __shared__ __align__(16) float ps[2][64][12];
    __shared__ float wcs[8][12];
    int b = blockIdx.x, chunk = blockIdx.y, tid = threadIdx.x;
    int warp = tid >> 5, lane = tid & 31;

    for (int i = tid; i < 11 * 256; i += 256) qs[i >> 8][i & 255] = g_q[b * 2816 + i];

    float U[11], csr[11];
    #pragma unroll
    for (int s = 0; s < 11; s++) { U[s] = 0.f; csr[s] = 0.f; }
    int nb = chunk * 256;

    // phase A: warp computes its 8 rows of segment `base`, writes p into ps[buf]
    auto phaseA = [&](int base, int buf) {
        #pragma unroll 1
        for (int rr = 0; rr < 8; rr += 2) {
            int nl = base + warp * 8 + rr;
            const float4* k0 = (const float4*)&g_kf[((size_t)(b * 4096 + nb + nl)) * 256];
            const float4* k1 = (const float4*)&g_kf[((size_t)(b * 4096 + nb + nl + 1)) * 256];
            float acc[2][11];
            #pragma unroll
            for (int s = 0; s < 11; s++) { acc[0][s] = 0.f; acc[1][s] = 0.f; }
            #pragma unroll
            for (int i = 0; i < 2; i++) {
                float4 ka = k0[i * 32 + lane];
                float4 kb = k1[i * 32 + lane];
                #pragma unroll
                for (int s = 0; s < 11; s++) {
                    float4 qv = *(const float4*)&qs[s][(i * 32 + lane) * 4];
                    acc[0][s] += ka.x * qv.x + ka.y * qv.y + ka.z * qv.z + ka.w * qv.w;
                    acc[1][s] += kb.x * qv.x + kb.y * qv.y + kb.z * qv.z + kb.w * qv.w;
                }
            }
            #pragma unroll
            for (int off = 16; off; off >>= 1) {
                #pragma unroll
                for (int s = 0; s < 11; s++) {
                    acc[0][s] += __shfl_xor_sync(0xffffffffu, acc[0][s], off);
                    acc[1][s] += __shfl_xor_sync(0xffffffffu, acc[1][s], off);
                }
            }
            #pragma unroll
            for (int r2 = 0; r2 < 2; r2++) {
                float m = acc[r2][0];
                #pragma unroll
                for (int s = 1; s < 11; s++) m = fmaxf(m, acc[r2][s]);
                float e[11], sum = 0.f;
                #pragma unroll
                for (int s = 0; s < 11; s++) { e[s] = expf(acc[r2][s] - m); sum += e[s]; }
                float inv = 1.f / sum;
                #pragma unroll
                for (int s = 0; s < 11; s++) {
                    float p = e[s] * inv + 1e-8f;
                    csr[s] += p;
                    if (lane == 0) ps[buf][warp * 8 + rr + r2][s] = p;
                }
            }
        }
    };

    __syncthreads();   // qs visible to all warps before first phase A
    phaseA(0, 0);
    for (int sub = 0; sub < 4; sub++) {
        __syncthreads();
        // phase B for segment sub (reads ps[sub&1])
        const float* vp = &g_vf[((size_t)(b * 4096 + nb + sub * 64)) * 256 + tid];
        const float(*pp)[12] = ps[sub & 1];
        #pragma unroll 8
        for (int n = 0; n < 64; n++) {
            float v = vp[(size_t)n * 256];
            const float4* p4 = (const float4*)&pp[n][0];
            float4 A0 = p4[0], A1 = p4[1], A2 = p4[2];
            U[0] += A0.x * v; U[1] += A0.y * v; U[2]  += A0.z * v; U[3] += A0.w * v;
            U[4] += A1.x * v; U[5] += A1.y * v; U[6]  += A1.z * v; U[7] += A1.w * v;
            U[8] += A2.x * v; U[9] += A2.y * v; U[10] += A2.z * v;
        }
        if (sub < 3) phaseA((sub + 1) * 64, (sub + 1) & 1);
    }

    float* up = &g_updraw[((size_t)b * 11) * 256 + tid];
    #pragma unroll
    for (int s = 0; s < 11; s++) atomicAdd(&up[s * 256], U[s]);

    if (lane == 0) {
        #pragma unroll
        for (int s = 0; s < 11; s++) wcs[warp][s] = csr[s];
    }
    __syncthreads();
    if (tid < 11) {
        float c = 0.f;
        #pragma unroll
        for (int w = 0; w < 8; w++) c += wcs[w][tid];
        atomicAdd(&g_colsum[b * 11 + tid], c);
    }
}

// ---------------- 5) gx = (U / colsum) @ gru_wi ----------------
__global__ void __launch_bounds__(256) k_gx(const float* __restrict__ wi)
{
    __shared__ __align__(16) float ins[256 * 12];
    __shared__ float sinv[11];
    int b = blockIdx.x, jt = blockIdx.y, tid = threadIdx.x;
    if (tid < 11) sinv[tid] = 1.f / g_colsum[b * 11 + tid];
    __syncthreads();
    for (int i = tid; i < 11 * 256; i += 256) {
        int s = i >> 8, k = i & 255;
        ins[k * 12 + s] = g_updraw[((size_t)b * 11 + s) * 256 + k] * sinv[s];
    }
    __syncthreads();

    int j = jt * 256 + tid;
    float acc[11];
    #pragma unroll
    for (int s = 0; s < 11; s++) acc[s] = 0.f;
    const float* wp = wi + j;
    #pragma unroll 2
    for (int k = 0; k < 256; k++) {
        float w = wp[(size_t)k * 768];
        const float4* s4 = (const float4*)&ins[k * 12];
        float4 A0 = s4[0], A1 = s4[1], A2 = s4[2];
        acc[0] += A0.x * w; acc[1] += A0.y * w; acc[2]  += A0.z * w; acc[3] += A0.w * w;
        acc[4] += A1.x * w; acc[5] += A1.y * w; acc[6]  += A1.z * w; acc[7] += A1.w * w;
        acc[8] += A2.x * w; acc[9] += A2.y * w; acc[10] += A2.z * w;
    }
    #pragma unroll
    for (int s = 0; s < 11; s++)
        g_gx[((size_t)b * 11 + s) * 768 + j] = acc[s];
}

// ---------------- 6) GRU scan, cp.async smem-staged weights ----------------
#define GRU_SMEM ((512 + 2 * 32 * 512 + 2 * 32 * 256) * 4)

__global__ void __launch_bounds__(256) k_gru(const float* __restrict__ wh,
                                             const float* __restrict__ gb,
                                             float* __restrict__ slots)
{
    extern __shared__ __align__(16) float sm[];
    float* hs = sm;
    float* rh = sm + 256;
    float* swzr = sm + 512;
    float* swa  = sm + 512 + 2 * 32 * 512;
    uint32_t szr_u = smem_u32(swzr);
    uint32_t sa_u  = smem_u32(swa);

    int b = blockIdx.x;
    int tid = threadIdx.x;
    hs[tid] = 0.f;
    float bz = gb[tid], br = gb[256 + tid], ba = gb[512 + tid];
    __syncthreads();

    for (int s = 0; s < 11; s++) {
        const float* gx = &g_gx[((size_t)b * 11 + s) * 768];
        float az0 = gx[tid] + bz, az1 = 0.f;
        float ar0 = gx[256 + tid] + br, ar1 = 0.f;

        {
            #pragma unroll
            for (int i = 0; i < 16; i++) {
                int idx = tid + i * 256;
                int row = idx >> 7, c4 = idx & 127;
                cp16(szr_u + (row * 512 + c4 * 4) * 4, wh + (size_t)row * 768 + c4 * 4);
            }
            cp_commit();
            for (int c = 0; c < 8; c++) {
                if (c < 7) {
                    int st = (c + 1) & 1;
                    int k0 = (c + 1) * 32;
                    #pragma unroll
                    for (int i = 0; i < 16; i++) {
                        int idx = tid + i * 256;
                        int row = idx >> 7, c4 = idx & 127;
                        cp16(szr_u + (st * 32 * 512 + row * 512 + c4 * 4) * 4,
                             wh + (size_t)(k0 + row) * 768 + c4 * 4);
                    }
                    cp_commit();
                    cp_wait1();
                } else {
                    cp_wait0();
                }
                __syncthreads();
                const float* w = swzr + (c & 1) * 32 * 512;
                int kb = c * 32;
                #pragma unroll 4
                for (int kk = 0; kk < 32; kk += 2) {
                    float h0 = hs[kb + kk], h1 = hs[kb + kk + 1];
                    az0 = fmaf(h0, w[kk * 512 + tid], az0);
                    ar0 = fmaf(h0, w[kk * 512 + 256 + tid], ar0);
                    az1 = fmaf(h1, w[(kk + 1) * 512 + tid], az1);
                    ar1 = fmaf(h1, w[(kk + 1) * 512 + 256 + tid], ar1);
                }
                __syncthreads();
            }
        }
        float z = 1.f / (1.f + expf(-(az0 + az1)));
        float r = 1.f / (1.f + expf(-(ar0 + ar1)));
        float hold = hs[tid];
        rh[tid] = r * hold;
        __syncthreads();

        float aa0 = gx[512 + tid] + ba, aa1 = 0.f;
        {
            #pragma unroll
            for (int i = 0; i < 8; i++) {
                int idx = tid + i * 256;
                int row = idx >> 6, c4 = idx & 63;
                cp16(sa_u + (row * 256 + c4 * 4) * 4, wh + (size_t)row * 768 + 512 + c4 * 4);
            }
            cp_commit();
            for (int c = 0; c < 8; c++) {
                if (c < 7) {
                    int st = (c + 1) & 1;
                    int k0 = (c + 1) * 32;
                    #pragma unroll
                    for (int i = 0; i < 8; i++) {
                        int idx = tid + i * 256;
                        int row = idx >> 6, c4 = idx & 63;
                        cp16(sa_u + (st * 32 * 256 + row * 256 + c4 * 4) * 4,
                             wh + (size_t)(k0 + row) * 768 + 512 + c4 * 4);
                    }
                    cp_commit();
                    cp_wait1();
                } else {
                    cp_wait0();
                }
                __syncthreads();
                const float* w = swa + (c & 1) * 32 * 256;
                int kb = c * 32;
                #pragma unroll 4
                for (int kk = 0; kk < 32; kk += 2) {
                    aa0 = fmaf(rh[kb + kk], w[kk * 256 + tid], aa0);
                    aa1 = fmaf(rh[kb + kk + 1], w[(kk + 1) * 256 + tid], aa1);
                }
                __syncthreads();
            }
        }
        float a = tanhf(aa0 + aa1);
        float hn = (1.f - z) * hold + z * a;
        slots[((size_t)b * 11 + s) * 256 + tid] = hn;
        __syncthreads();
        hs[tid] = hn;
        __syncthreads();
    }
}

// ---------------- 7) fused MLP + next-iteration q: slots += MLP; q = LN(slots)@Wq*scale ----------------
__global__ void __launch_bounds__(256) k_mlpq(const float* __restrict__ g, const float* __restrict__ o,
                                              const float* __restrict__ w1, const float* __restrict__ b1,
                                              const float* __restrict__ w2, const float* __restrict__ b2,
                                              const float* __restrict__ gq, const float* __restrict__ oq,
                                              const float* __restrict__ Wq,
                                              float* __restrict__ slots)
{
    __shared__ float lns[256];
    __shared__ float hid[512];
    int r = blockIdx.x, tid = threadIdx.x;
    float val = slots[r * 256 + tid];
    float s_ = val, q_ = val * val;
    block_reduce2(s_, q_);
    float muv = s_ * (1.f / 256.f);
    float var = q_ * (1.f / 256.f) - muv * muv;
    float rs = rsqrtf(var + 1e-5f);
    lns[tid] = (val - muv) * rs * g[tid] + o[tid];
    __syncthreads();

    const float2* wp = (const float2*)&w1[tid * 2];
    float ax0 = 0.f, ay0 = 0.f, ax1 = 0.f, ay1 = 0.f;
    #pragma unroll 4
    for (int k = 0; k < 256; k += 2) {
        float l0 = lns[k], l1 = lns[k + 1];
        float2 w0 = wp[(size_t)k * 256];
        float2 w1v = wp[(size_t)(k + 1) * 256];
        ax0 = fmaf(l0, w0.x, ax0); ay0 = fmaf(l0, w0.y, ay0);
        ax1 = fmaf(l1, w1v.x, ax1); ay1 = fmaf(l1, w1v.y, ay1);
    }
    float2 bb = *(const float2*)&b1[tid * 2];
    hid[tid * 2]     = fmaxf(ax0 + ax1 + bb.x, 0.f);
    hid[tid * 2 + 1] = fmaxf(ay0 + ay1 + bb.y, 0.f);
    __syncthreads();

    const float* w2p = w2 + tid;
    float a0 = 0.f, a1 = 0.f, a2 = 0.f, a3 = 0.f;
    #pragma unroll 4
    for (int k = 0; k < 512; k += 4) {
        a0 = fmaf(hid[k],     w2p[(size_t)k * 256],       a0);
        a1 = fmaf(hid[k + 1], w2p[(size_t)(k + 1) * 256], a1);
        a2 = fmaf(hid[k + 2], w2p[(size_t)(k + 2) * 256], a2);
        a3 = fmaf(hid[k + 3], w2p[(size_t)(k + 3) * 256], a3);
    }
    float sv = val + ((a0 + a1) + (a2 + a3)) + b2[tid];
    slots[r * 256 + tid] = sv;

    // ---- next-iteration head: zero accum, LN(sv), q = LN@Wq*scale ----
    g_updraw[r * 256 + tid] = 0.f;
    if (tid == 0) g_colsum[r] = 0.f;

    float s2 = sv, q2 = sv * sv;
    block_reduce2(s2, q2);
    float mu2 = s2 * (1.f / 256.f);
    float v2 = q2 * (1.f / 256.f) - mu2 * mu2;
    float rs2 = rsqrtf(v2 + 1e-5f);
    __syncthreads();
    lns[tid] = (sv - mu2) * rs2 * gq[tid] + oq[tid];
    __syncthreads();

    const float* wq = Wq + tid;
    float b0 = 0.f, b1_ = 0.f, b2_ = 0.f, b3 = 0.f;
    #pragma unroll 4
    for (int k = 0; k < 256; k += 4) {
        b0  = fmaf(lns[k],     wq[(size_t)k * 256],       b0);
        b1_ = fmaf(lns[k + 1], wq[(size_t)(k + 1) * 256], b1_);
        b2_ = fmaf(lns[k + 2], wq[(size_t)(k + 2) * 256], b2_);
        b3  = fmaf(lns[k + 3], wq[(size_t)(k + 3) * 256], b3);
    }
    g_q[r * 256 + tid] = ((b0 + b1_) + (b2_ + b3)) * 0.0625f;
}

// ---------------- host launch ----------------
extern "C" void kernel_launch(void* const* d_in, const int* in_sizes, int n_in,
                              void* d_out, int out_size)
{
    const float* inputs          = (const float*)d_in[0];
    const float* slot_noise      = (const float*)d_in[1];
    const float* ln_in_scale     = (const float*)d_in[2];
    const float* ln_in_offset    = (const float*)d_in[3];
    const float* ln_slots_scale  = (const float*)d_in[4];
    const float* ln_slots_offset = (const float*)d_in[5];
    const float* ln_mlp_scale    = (const float*)d_in[6];
    const float* ln_mlp_offset   = (const float*)d_in[7];
    const float* slots_mu        = (const float*)d_in[8];
    const float* slots_log_sigma = (const float*)d_in[9];
    const float* Wq              = (const float*)d_in[10];
    const float* Wk              = (const float*)d_in[11];
    const float* Wv              = (const float*)d_in[12];
    const float* gru_wi          = (const float*)d_in[13];
    const float* gru_wh          = (const float*)d_in[14];
    const float* gru_b           = (const float*)d_in[15];
    const float* mlp_w1          = (const float*)d_in[16];
    const float* mlp_b1          = (const float*)d_in[17];
    const float* mlp_w2          = (const float*)d_in[18];
    const float* mlp_b2          = (const float*)d_in[19];
    float* slots = (float*)d_out;

    (void)in_sizes; (void)n_in; (void)out_size;

    cudaFuncSetAttribute(k_mma_kv, cudaFuncAttributeMaxDynamicSharedMemorySize, SMEM_SZ);
    cudaFuncSetAttribute(k_gru, cudaFuncAttributeMaxDynamicSharedMemorySize, GRU_SMEM);

    k_q<<<352, 256>>>(slot_noise, slots_mu, slots_log_sigma,
                      ln_slots_scale, ln_slots_offset, Wq, slots);            // 0
    k_prepall<<<16384 + 512, 256>>>(inputs, ln_in_scale, ln_in_offset, Wk, Wv); // 1
    k_mma_kv<<<dim3(4, (B_ * N_) / 128), 512, SMEM_SZ>>>();                   // 2

    for (int it = 0; it < 3; it++) {
        k_attn_upd<<<dim3(32, 16), 256>>>();                                  // 3 at it=0 (profiled)
        k_gx<<<dim3(32, 3), 256>>>(gru_wi);
        k_gru<<<32, 256, GRU_SMEM>>>(gru_wh, gru_b, slots);
        k_mlpq<<<352, 256>>>(ln_mlp_scale, ln_mlp_offset, mlp_w1, mlp_b1, mlp_w2, mlp_b2,
                             ln_slots_scale, ln_slots_offset, Wq, slots);
    }
}

// round 8
// speedup vs baseline: 1.0019x; 1.0019x over previous
#include <cuda_runtime.h>
#include <cuda_bf16.h>
#include <stdint.h>

#define B_ 32
#define N_ 4096
#define D_ 256
#define S_ 11
#define H_ 256
#define M_ 512

// ---------------- scratch (static device globals; no allocs) ----------------
__device__ __nv_bfloat16 g_ahi[(size_t)B_*N_*D_];
__device__ __nv_bfloat16 g_alo[(size_t)B_*N_*D_];
__device__ __nv_bfloat16 g_wthi[512*256];
__device__ __nv_bfloat16 g_wtlo[512*256];
__device__ float g_kf[(size_t)B_*N_*H_];
__device__ float g_vf[(size_t)B_*N_*H_];
__device__ float g_colsum[B_*S_];
__device__ float g_q[B_*S_*H_];
__device__ float g_updraw[B_*S_*H_];
__device__ float g_gx[B_*S_*3*H_];

// ---------------- helpers ----------------
__device__ __forceinline__ uint32_t smem_u32(const void* p) {
    uint32_t a;
    asm("{ .reg .u64 t; cvta.to.shared.u64 t, %1; cvt.u32.u64 %0, t; }" : "=r"(a) : "l"(p));
    return a;
}
__device__ __forceinline__ void ldsm_x4(uint32_t& r0, uint32_t& r1, uint32_t& r2, uint32_t& r3,
                                        uint32_t addr) {
    asm volatile("ldmatrix.sync.aligned.m8n8.x4.shared.b16 {%0,%1,%2,%3}, [%4];"
                 : "=r"(r0), "=r"(r1), "=r"(r2), "=r"(r3) : "r"(addr));
}
__device__ __forceinline__ void mma16816(float* d, const uint32_t* a, const uint32_t* b) {
    asm volatile("mma.sync.aligned.m16n8k16.row.col.f32.bf16.bf16.f32 "
                 "{%0,%1,%2,%3}, {%4,%5,%6,%7}, {%8,%9}, {%0,%1,%2,%3};"
                 : "+f"(d[0]), "+f"(d[1]), "+f"(d[2]), "+f"(d[3])
                 : "r"(a[0]), "r"(a[1]), "r"(a[2]), "r"(a[3]), "r"(b[0]), "r"(b[1]));
}
__device__ __forceinline__ void cp16(uint32_t saddr, const void* g) {
    asm volatile("cp.async.cg.shared.global [%0], [%1], 16;" :: "r"(saddr), "l"(g));
}
__device__ __forceinline__ void cp_commit() { asm volatile("cp.async.commit_group;" ::: "memory"); }
__device__ __forceinline__ void cp_wait1()  { asm volatile("cp.async.wait_group 1;" ::: "memory"); }
__device__ __forceinline__ void cp_wait0()  { asm volatile("cp.async.wait_group 0;" ::: "memory"); }

__device__ __forceinline__ void block_reduce2(float& s, float& q) {
    #pragma unroll
    for (int off = 16; off; off >>= 1) {
        s += __shfl_xor_sync(0xffffffffu, s, off);
        q += __shfl_xor_sync(0xffffffffu, q, off);
    }
    __shared__ float ss[8], sq[8];
    int w = threadIdx.x >> 5, l = threadIdx.x & 31;
    if (l == 0) { ss[w] = s; sq[w] = q; }
    __syncthreads();
    s = 0.f; q = 0.f;
    #pragma unroll
    for (int i = 0; i < 8; i++) { s += ss[i]; q += sq[i]; }
}

// ---------------- 1) k_q: init slots + zero accum + LN(slots) + q = LN@Wq*scale ----------------
__global__ void __launch_bounds__(256) k_q(const float* __restrict__ noise,
                                           const float* __restrict__ mu, const float* __restrict__ ls,
                                           const float* __restrict__ g, const float* __restrict__ o,
                                           const float* __restrict__ Wq, float* __restrict__ slots)
{
    __shared__ float lns[256];
    int r = blockIdx.x, tid = threadIdx.x;
    float val = mu[tid] + expf(ls[tid]) * noise[r * 256 + tid];
    slots[r * 256 + tid] = val;
    g_updraw[r * 256 + tid] = 0.f;
    if (tid == 0) g_colsum[r] = 0.f;

    float s_ = val, q_ = val * val;
    block_reduce2(s_, q_);
    float muv = s_ * (1.f / 256.f);
    float var = q_ * (1.f / 256.f) - muv * muv;
    float rs = rsqrtf(var + 1e-5f);
    lns[tid] = (val - muv) * rs * g[tid] + o[tid];
    __syncthreads();

    const float* wp = Wq + tid;
    float a0 = 0.f, a1 = 0.f, a2 = 0.f, a3 = 0.f;
    #pragma unroll 4
    for (int k = 0; k < 256; k += 4) {
        a0 = fmaf(lns[k],     wp[(size_t)k * 256],       a0);
        a1 = fmaf(lns[k + 1], wp[(size_t)(k + 1) * 256], a1);
        a2 = fmaf(lns[k + 2], wp[(size_t)(k + 2) * 256], a2);
        a3 = fmaf(lns[k + 3], wp[(size_t)(k + 3) * 256], a3);
    }
    g_q[r * 256 + tid] = ((a0 + a1) + (a2 + a3)) * 0.0625f;
}

// ---------------- 2) combined input-prep + weight-prep ----------------
__global__ void __launch_bounds__(256) k_prepall(const float* __restrict__ x,
                                                 const float* __restrict__ g,
                                                 const float* __restrict__ o,
                                                 const float* __restrict__ wk,
                                                 const float* __restrict__ wv)
{
    if (blockIdx.x >= 16384) {
        int idx = (blockIdx.x - 16384) * 256 + threadIdx.x;
        int j = idx >> 8;
        int k = idx & 255;
        float w = (j < 256) ? wk[k * 256 + j] : wv[k * 256 + (j - 256)];
        __nv_bfloat16 h = __float2bfloat16_rn(w);
        g_wthi[idx] = h;
        g_wtlo[idx] = __float2bfloat16_rn(w - __bfloat162float(h));
        return;
    }
    int wid = threadIdx.x >> 5, lane = threadIdx.x & 31;
    int row = blockIdx.x * 8 + wid;
    const float4* xp = (const float4*)&x[(size_t)row * 256 + lane * 8];
    float4 a = xp[0], b = xp[1];
    float s = a.x + a.y + a.z + a.w + b.x + b.y + b.z + b.w;
    float q = a.x*a.x + a.y*a.y + a.z*a.z + a.w*a.w
            + b.x*b.x + b.y*b.y + b.z*b.z + b.w*b.w;
    #pragma unroll
    for (int off = 16; off; off >>= 1) {
        s += __shfl_xor_sync(0xffffffffu, s, off);
        q += __shfl_xor_sync(0xffffffffu, q, off);
    }
    float mu = s * (1.f / 256.f);
    float var = q * (1.f / 256.f) - mu * mu;
    float rs = rsqrtf(var + 1e-5f);

    const float4* gp = (const float4*)&g[lane * 8];
    const float4* op = (const float4*)&o[lane * 8];
    float4 g0 = gp[0], g1 = gp[1], o0 = op[0], o1 = op[1];

    float v[8];
    v[0] = (a.x - mu) * rs * g0.x + o0.x;
    v[1] = (a.y - mu) * rs * g0.y + o0.y;
    v[2] = (a.z - mu) * rs * g0.z + o0.z;
    v[3] = (a.w - mu) * rs * g0.w + o0.w;
    v[4] = (b.x - mu) * rs * g1.x + o1.x;
    v[5] = (b.y - mu) * rs * g1.y + o1.y;
    v[6] = (b.z - mu) * rs * g1.z + o1.z;
    v[7] = (b.w - mu) * rs * g1.w + o1.w;

    float hf[8], lf[8];
    #pragma unroll
    for (int i = 0; i < 8; i++) {
        __nv_bfloat16 h = __float2bfloat16_rn(v[i]);
        hf[i] = __bfloat162float(h);
        lf[i] = v[i] - hf[i];
    }
    __nv_bfloat162 h01 = __floats2bfloat162_rn(hf[0], hf[1]);
    __nv_bfloat162 h23 = __floats2bfloat162_rn(hf[2], hf[3]);
    __nv_bfloat162 h45 = __floats2bfloat162_rn(hf[4], hf[5]);
    __nv_bfloat162 h67 = __floats2bfloat162_rn(hf[6], hf[7]);
    __nv_bfloat162 l01 = __floats2bfloat162_rn(lf[0], lf[1]);
    __nv_bfloat162 l23 = __floats2bfloat162_rn(lf[2], lf[3]);
    __nv_bfloat162 l45 = __floats2bfloat162_rn(lf[4], lf[5]);
    __nv_bfloat162 l67 = __floats2bfloat162_rn(lf[6], lf[7]);
    uint4 uh, ul;
    uh.x = *(uint32_t*)&h01; uh.y = *(uint32_t*)&h23; uh.z = *(uint32_t*)&h45; uh.w = *(uint32_t*)&h67;
    ul.x = *(uint32_t*)&l01; ul.y = *(uint32_t*)&l23; ul.z = *(uint32_t*)&l45; ul.w = *(uint32_t*)&l67;
    *(uint4*)&g_ahi[(size_t)row * 256 + lane * 8] = uh;
    *(uint4*)&g_alo[(size_t)row * 256 + lane * 8] = ul;
}

// ---------------- 3) mma.sync split-bf16 GEMM, 256 threads, 32x64 warp tiles (R5 config) ----------------
#define SM_AH 0
#define SM_AL 16384
#define SM_BH 32768
#define SM_BL 49152
#define STAGE_SZ 65536
#define SMEM_SZ (2 * STAGE_SZ)

__device__ __forceinline__ void mma_fill(uint32_t sb, int st, int rowbase, size_t jb, int kb, int tid) {
    uint32_t so = st * STAGE_SZ;
    #pragma unroll
    for (int i = 0; i < 4; i++) {
        int idx = tid + i * 256;
        int row = idx >> 3, c8 = idx & 7;
        uint32_t bo = row * 128 + c8 * 16;
        uint32_t sw = (bo ^ ((bo >> 3) & 0x70)) + so;
        size_t srcA = (size_t)(rowbase + row) * 256 + kb + c8 * 8;
        size_t srcB = jb + (size_t)row * 256 + kb + c8 * 8;
        cp16(sb + SM_AH + sw, &g_ahi[srcA]);
        cp16(sb + SM_AL + sw, &g_alo[srcA]);
        cp16(sb + SM_BH + sw, &g_wthi[srcB]);
        cp16(sb + SM_BL + sw, &g_wtlo[srcB]);
    }
    cp_commit();
}

__global__ void __launch_bounds__(256, 1) k_mma_kv()
{
    extern __shared__ __align__(1024) uint8_t smem[];
    uint32_t sbase = smem_u32(smem);
    int tid = threadIdx.x;
    int lane = tid & 31;
    int warp = tid >> 5;
    int wm = warp & 3;
    int wn = warp >> 2;

    int half = blockIdx.x >> 1;
    int ntile = blockIdx.x & 1;
    int rowbase = blockIdx.y * 128;
    size_t jb = ((size_t)half * 256 + ntile * 128) * 256;

    float acc[2][8][4];
    #pragma unroll
    for (int mf = 0; mf < 2; mf++)
        #pragma unroll
        for (int nf = 0; nf < 8; nf++)
            #pragma unroll
            for (int r = 0; r < 4; r++) acc[mf][nf][r] = 0.f;

    uint32_t lrow = ((lane >> 3) & 1) * 8 + (lane & 7);
    uint32_t lcol = ((lane >> 4) & 1) * 16;

    mma_fill(sbase, 0, rowbase, jb, 0, tid);
    mma_fill(sbase, 1, rowbase, jb, 64, tid);

    for (int ch = 0; ch < 4; ch++) {
        if (ch < 3) cp_wait1();
        else        cp_wait0();
        __syncthreads();
        uint32_t so = (ch & 1) * STAGE_SZ;

        #pragma unroll
        for (int ks = 0; ks < 4; ks++) {
            uint32_t cb = ks * 32 + lcol;
            uint32_t ah[2][4], al[2][4];
            #pragma unroll
            for (int mf = 0; mf < 2; mf++) {
                uint32_t r = wm * 32 + mf * 16 + lrow;
                uint32_t bo = r * 128 + cb;
                uint32_t sw = (bo ^ ((bo >> 3) & 0x70)) + so;
                ldsm_x4(ah[mf][0], ah[mf][1], ah[mf][2], ah[mf][3], sbase + SM_AH + sw);
                ldsm_x4(al[mf][0], al[mf][1], al[mf][2], al[mf][3], sbase + SM_AL + sw);
            }
            uint32_t bh[8][2], bl[8][2];
            #pragma unroll
            for (int g = 0; g < 4; g++) {
                uint32_t r = wn * 64 + g * 16 + lrow;
                uint32_t bo = r * 128 + cb;
                uint32_t sw = (bo ^ ((bo >> 3) & 0x70)) + so;
                uint32_t t0, t1, t2, t3;
                ldsm_x4(t0, t1, t2, t3, sbase + SM_BH + sw);
                bh[g * 2][0] = t0; bh[g * 2 + 1][0] = t1;
                bh[g * 2][1] = t2; bh[g * 2 + 1][1] = t3;
                ldsm_x4(t0, t1, t2, t3, sbase + SM_BL + sw);
                bl[g * 2][0] = t0; bl[g * 2 + 1][0] = t1;
                bl[g * 2][1] = t2; bl[g * 2 + 1][1] = t3;
            }
            #pragma unroll
            for (int mf = 0; mf < 2; mf++)
                #pragma unroll
                for (int nf = 0; nf < 8; nf++) {
                    mma16816(acc[mf][nf], ah[mf], bh[nf]);
                    mma16816(acc[mf][nf], ah[mf], bl[nf]);
                    mma16816(acc[mf][nf], al[mf], bh[nf]);
                }
        }
        __syncthreads();
        if (ch < 2) mma_fill(sbase, ch & 1, rowbase, jb, (ch + 2) * 64, tid);
    }

    float* outp = (half == 0) ? g_kf : g_vf;
    int r0 = rowbase + wm * 32 + (lane >> 2);
    int c0 = ntile * 128 + wn * 64 + (lane & 3) * 2;
    #pragma unroll
    for (int mf = 0; mf < 2; mf++)
        #pragma unroll
        for (int nf = 0; nf < 8; nf++) {
            float* d = acc[mf][nf];
            size_t base = (size_t)(r0 + mf * 16) * 256 + c0 + nf * 8;
            *(float2*)&outp[base] = make_float2(d[0], d[1]);
            *(float2*)&outp[base + 8 * 256] = make_float2(d[2], d[3]);
        }
}

// ---------------- 4) fused attention, double-buffered p, 1 sync per 64-row segment ----------------
__global__ void __launch_bounds__(256, 2) k_attn_upd()
{
    __shared__ __align__(16) float qs[11][256];
    __shared__ __align__(16) float ps[2][64][12];
    __shared__ float wcs[8][12];
    int b = blockIdx.x, chunk = blockIdx.y, tid = threadIdx.x;
    int warp = tid >> 5, lane = tid & 31;

    for (int i = tid; i < 11 * 256; i += 256) qs[i >> 8][i & 255] = g_q[b * 2816 + i];

    float U[11], csr[11];
    #pragma unroll
    for (int s = 0; s < 11; s++) { U[s] = 0.f; csr[s] = 0.f; }
    int nb = chunk * 256;

    auto phaseA = [&](int base, int buf) {
        #pragma unroll 1
        for (int rr = 0; rr < 8; rr += 2) {
            int nl = base + warp * 8 + rr;
            const float4* k0 = (const float4*)&g_kf[((size_t)(b * 4096 + nb + nl)) * 256];
            const float4* k1 = (const float4*)&g_kf[((size_t)(b * 4096 + nb + nl + 1)) * 256];
            float acc[2][11];
            #pragma unroll
            for (int s = 0; s < 11; s++) { acc[0][s] = 0.f; acc[1][s] = 0.f; }
            #pragma unroll
            for (int i = 0; i < 2; i++) {
                float4 ka = k0[i * 32 + lane];
                float4 kb = k1[i * 32 + lane];
                #pragma unroll
                for (int s = 0; s < 11; s++) {
                    float4 qv = *(const float4*)&qs[s][(i * 32 + lane) * 4];
                    acc[0][s] += ka.x * qv.x + ka.y * qv.y + ka.z * qv.z + ka.w * qv.w;
                    acc[1][s] += kb.x * qv.x + kb.y * qv.y + kb.z * qv.z + kb.w * qv.w;
                }
            }
            #pragma unroll
            for (int off = 16; off; off >>= 1) {
                #pragma unroll
                for (int s = 0; s < 11; s++) {
                    acc[0][s] += __shfl_xor_sync(0xffffffffu, acc[0][s], off);
                    acc[1][s] += __shfl_xor_sync(0xffffffffu, acc[1][s], off);
                }
            }
            #pragma unroll
            for (int r2 = 0; r2 < 2; r2++) {
                float m = acc[r2][0];
                #pragma unroll
                for (int s = 1; s < 11; s++) m = fmaxf(m, acc[r2][s]);
                float e[11], sum = 0.f;
                #pragma unroll
                for (int s = 0; s < 11; s++) { e[s] = expf(acc[r2][s] - m); sum += e[s]; }
                float inv = 1.f / sum;
                #pragma unroll
                for (int s = 0; s < 11; s++) {
                    float p = e[s] * inv + 1e-8f;
                    csr[s] += p;
                    if (lane == 0) ps[buf][warp * 8 + rr + r2][s] = p;
                }
            }
        }
    };

    __syncthreads();   // qs visible to all warps before first phase A
    phaseA(0, 0);
    for (int sub = 0; sub < 4; sub++) {
        __syncthreads();
        const float* vp = &g_vf[((size_t)(b * 4096 + nb + sub * 64)) * 256 + tid];
        const float(*pp)[12] = ps[sub & 1];
        #pragma unroll 8
        for (int n = 0; n < 64; n++) {
            float v = vp[(size_t)n * 256];
            const float4* p4 = (const float4*)&pp[n][0];
            float4 A0 = p4[0], A1 = p4[1], A2 = p4[2];
            U[0] += A0.x * v; U[1] += A0.y * v; U[2]  += A0.z * v; U[3] += A0.w * v;
            U[4] += A1.x * v; U[5] += A1.y * v; U[6]  += A1.z * v; U[7] += A1.w * v;
            U[8] += A2.x * v; U[9] += A2.y * v; U[10] += A2.z * v;
        }
        if (sub < 3) phaseA((sub + 1) * 64, (sub + 1) & 1);
    }

    float* up = &g_updraw[((size_t)b * 11) * 256 + tid];
    #pragma unroll
    for (int s = 0; s < 11; s++) atomicAdd(&up[s * 256], U[s]);

    if (lane == 0) {
        #pragma unroll
        for (int s = 0; s < 11; s++) wcs[warp][s] = csr[s];
    }
    __syncthreads();
    if (tid < 11) {
        float c = 0.f;
        #pragma unroll
        for (int w = 0; w < 8; w++) c += wcs[w][tid];
        atomicAdd(&g_colsum[b * 11 + tid], c);
    }
}

// ---------------- 5) gx = (U / colsum) @ gru_wi ----------------
__global__ void __launch_bounds__(256) k_gx(const float* __restrict__ wi)
{
    __shared__ __align__(16) float ins[256 * 12];
    __shared__ float sinv[11];
    int b = blockIdx.x, jt = blockIdx.y, tid = threadIdx.x;
    if (tid < 11) sinv[tid] = 1.f / g_colsum[b * 11 + tid];
    __syncthreads();
    for (int i = tid; i < 11 * 256; i += 256) {
        int s = i >> 8, k = i & 255;
        ins[k * 12 + s] = g_updraw[((size_t)b * 11 + s) * 256 + k] * sinv[s];
    }
    __syncthreads();

    int j = jt * 256 + tid;
    float acc[11];
    #pragma unroll
    for (int s = 0; s < 11; s++) acc[s] = 0.f;
    const float* wp = wi + j;
    #pragma unroll 2
    for (int k = 0; k < 256; k++) {
        float w = wp[(size_t)k * 768];
        const float4* s4 = (const float4*)&ins[k * 12];
        float4 A0 = s4[0], A1 = s4[1], A2 = s4[2];
        acc[0] += A0.x * w; acc[1] += A0.y * w; acc[2]  += A0.z * w; acc[3] += A0.w * w;
        acc[4] += A1.x * w; acc[5] += A1.y * w; acc[6]  += A1.z * w; acc[7] += A1.w * w;
        acc[8] += A2.x * w; acc[9] += A2.y * w; acc[10] += A2.z * w;
    }
    #pragma unroll
    for (int s = 0; s < 11; s++)
        g_gx[((size_t)b * 11 + s) * 768 + j] = acc[s];
}

// ---------------- 6) GRU scan, cp.async smem-staged weights ----------------
#define GRU_SMEM ((512 + 2 * 32 * 512 + 2 * 32 * 256) * 4)

__global__ void __launch_bounds__(256) k_gru(const float* __restrict__ wh,
                                             const float* __restrict__ gb,
                                             float* __restrict__ slots)
{
    extern __shared__ __align__(16) float sm[];
    float* hs = sm;
    float* rh = sm + 256;
    float* swzr = sm + 512;
    float* swa  = sm + 512 + 2 * 32 * 512;
    uint32_t szr_u = smem_u32(swzr);
    uint32_t sa_u  = smem_u32(swa);

    int b = blockIdx.x;
    int tid = threadIdx.x;
    hs[tid] = 0.f;
    float bz = gb[tid], br = gb[256 + tid], ba = gb[512 + tid];
    __syncthreads();

    for (int s = 0; s < 11; s++) {
        const float* gx = &g_gx[((size_t)b * 11 + s) * 768];
        float az0 = gx[tid] + bz, az1 = 0.f;
        float ar0 = gx[256 + tid] + br, ar1 = 0.f;

        {
            #pragma unroll
            for (int i = 0; i < 16; i++) {
                int idx = tid + i * 256;
                int row = idx >> 7, c4 = idx & 127;
                cp16(szr_u + (row * 512 + c4 * 4) * 4, wh + (size_t)row * 768 + c4 * 4);
            }
            cp_commit();
            for (int c = 0; c < 8; c++) {
                if (c < 7) {
                    int st = (c + 1) & 1;
                    int k0 = (c + 1) * 32;
                    #pragma unroll
                    for (int i = 0; i < 16; i++) {
                        int idx = tid + i * 256;
                        int row = idx >> 7, c4 = idx & 127;
                        cp16(szr_u + (st * 32 * 512 + row * 512 + c4 * 4) * 4,
                             wh + (size_t)(k0 + row) * 768 + c4 * 4);
                    }
                    cp_commit();
                    cp_wait1();
                } else {
                    cp_wait0();
                }
                __syncthreads();
                const float* w = swzr + (c & 1) * 32 * 512;
                int kb = c * 32;
                #pragma unroll 4
                for (int kk = 0; kk < 32; kk += 2) {
                    float h0 = hs[kb + kk], h1 = hs[kb + kk + 1];
                    az0 = fmaf(h0, w[kk * 512 + tid], az0);
                    ar0 = fmaf(h0, w[kk * 512 + 256 + tid], ar0);
                    az1 = fmaf(h1, w[(kk + 1) * 512 + tid], az1);
                    ar1 = fmaf(h1, w[(kk + 1) * 512 + 256 + tid], ar1);
                }
                __syncthreads();
            }
        }
        float z = 1.f / (1.f + expf(-(az0 + az1)));
        float r = 1.f / (1.f + expf(-(ar0 + ar1)));
        float hold = hs[tid];
        rh[tid] = r * hold;
        __syncthreads();

        float aa0 = gx[512 + tid] + ba, aa1 = 0.f;
        {
            #pragma unroll
            for (int i = 0; i < 8; i++) {
                int idx = tid + i * 256;
                int row = idx >> 6, c4 = idx & 63;
                cp16(sa_u + (row * 256 + c4 * 4) * 4, wh + (size_t)row * 768 + 512 + c4 * 4);
            }
            cp_commit();
            for (int c = 0; c < 8; c++) {
                if (c < 7) {
                    int st = (c + 1) & 1;
                    int k0 = (c + 1) * 32;
                    #pragma unroll
                    for (int i = 0; i < 8; i++) {
                        int idx = tid + i * 256;
                        int row = idx >> 6, c4 = idx & 63;
                        cp16(sa_u + (st * 32 * 256 + row * 256 + c4 * 4) * 4,
                             wh + (size_t)(k0 + row) * 768 + 512 + c4 * 4);
                    }
                    cp_commit();
                    cp_wait1();
                } else {
                    cp_wait0();
                }
                __syncthreads();
                const float* w = swa + (c & 1) * 32 * 256;
                int kb = c * 32;
                #pragma unroll 4
                for (int kk = 0; kk < 32; kk += 2) {
                    aa0 = fmaf(rh[kb + kk], w[kk * 256 + tid], aa0);
                    aa1 = fmaf(rh[kb + kk + 1], w[(kk + 1) * 256 + tid], aa1);
                }
                __syncthreads();
            }
        }
        float a = tanhf(aa0 + aa1);
        float hn = (1.f - z) * hold + z * a;
        slots[((size_t)b * 11 + s) * 256 + tid] = hn;
        __syncthreads();
        hs[tid] = hn;
        __syncthreads();
    }
}

// ---------------- 7) fused MLP + next-iteration q ----------------
__global__ void __launch_bounds__(256) k_mlpq(const float* __restrict__ g, const float* __restrict__ o,
                                              const float* __restrict__ w1, const float* __restrict__ b1,
                                              const float* __restrict__ w2, const float* __restrict__ b2,
                                              const float* __restrict__ gq, const float* __restrict__ oq,
                                              const float* __restrict__ Wq,
                                              float* __restrict__ slots)
{
    __shared__ float lns[256];
    __shared__ float hid[512];
    int r = blockIdx.x, tid = threadIdx.x;
    float val = slots[r * 256 + tid];
    float s_ = val, q_ = val * val;
    block_reduce2(s_, q_);
    float muv = s_ * (1.f / 256.f);
    float var = q_ * (1.f / 256.f) - muv * muv;
    float rs = rsqrtf(var + 1e-5f);
    lns[tid] = (val - muv) * rs * g[tid] + o[tid];
    __syncthreads();

    const float2* wp = (const float2*)&w1[tid * 2];
    float ax0 = 0.f, ay0 = 0.f, ax1 = 0.f, ay1 = 0.f;
    #pragma unroll 4
    for (int k = 0; k < 256; k += 2) {
        float l0 = lns[k], l1 = lns[k + 1];
        float2 w0 = wp[(size_t)k * 256];
        float2 w1v = wp[(size_t)(k + 1) * 256];
        ax0 = fmaf(l0, w0.x, ax0); ay0 = fmaf(l0, w0.y, ay0);
        ax1 = fmaf(l1, w1v.x, ax1); ay1 = fmaf(l1, w1v.y, ay1);
    }
    float2 bb = *(const float2*)&b1[tid * 2];
    hid[tid * 2]     = fmaxf(ax0 + ax1 + bb.x, 0.f);
    hid[tid * 2 + 1] = fmaxf(ay0 + ay1 + bb.y, 0.f);
    __syncthreads();

    const float* w2p = w2 + tid;
    float a0 = 0.f, a1 = 0.f, a2 = 0.f, a3 = 0.f;
    #pragma unroll 4
    for (int k = 0; k < 512; k += 4) {
        a0 = fmaf(hid[k],     w2p[(size_t)k * 256],       a0);
        a1 = fmaf(hid[k + 1], w2p[(size_t)(k + 1) * 256], a1);
        a2 = fmaf(hid[k + 2], w2p[(size_t)(k + 2) * 256], a2);
        a3 = fmaf(hid[k + 3], w2p[(size_t)(k + 3) * 256], a3);
    }
    float sv = val + ((a0 + a1) + (a2 + a3)) + b2[tid];
    slots[r * 256 + tid] = sv;

    g_updraw[r * 256 + tid] = 0.f;
    if (tid == 0) g_colsum[r] = 0.f;

    float s2 = sv, q2 = sv * sv;
    block_reduce2(s2, q2);
    float mu2 = s2 * (1.f / 256.f);
    float v2 = q2 * (1.f / 256.f) - mu2 * mu2;
    float rs2 = rsqrtf(v2 + 1e-5f);
    __syncthreads();
    lns[tid] = (sv - mu2) * rs2 * gq[tid] + oq[tid];
    __syncthreads();

    const float* wq = Wq + tid;
    float b0 = 0.f, b1_ = 0.f, b2_ = 0.f, b3 = 0.f;
    #pragma unroll 4
    for (int k = 0; k < 256; k += 4) {
        b0  = fmaf(lns[k],     wq[(size_t)k * 256],       b0);
        b1_ = fmaf(lns[k + 1], wq[(size_t)(k + 1) * 256], b1_);
        b2_ = fmaf(lns[k + 2], wq[(size_t)(k + 2) * 256], b2_);
        b3  = fmaf(lns[k + 3], wq[(size_t)(k + 3) * 256], b3);
    }
    g_q[r * 256 + tid] = ((b0 + b1_) + (b2_ + b3)) * 0.0625f;
}

// ---------------- host launch ----------------
extern "C" void kernel_launch(void* const* d_in, const int* in_sizes, int n_in,
                              void* d_out, int out_size)
{
    const float* inputs          = (const float*)d_in[0];
    const float* slot_noise      = (const float*)d_in[1];
    const float* ln_in_scale     = (const float*)d_in[2];
    const float* ln_in_offset    = (const float*)d_in[3];
    const float* ln_slots_scale  = (const float*)d_in[4];
    const float* ln_slots_offset = (const float*)d_in[5];
    const float* ln_mlp_scale    = (const float*)d_in[6];
    const float* ln_mlp_offset   = (const float*)d_in[7];
    const float* slots_mu        = (const float*)d_in[8];
    const float* slots_log_sigma = (const float*)d_in[9];
    const float* Wq              = (const float*)d_in[10];
    const float* Wk              = (const float*)d_in[11];
    const float* Wv              = (const float*)d_in[12];
    const float* gru_wi          = (const float*)d_in[13];
    const float* gru_wh          = (const float*)d_in[14];
    const float* gru_b           = (const float*)d_in[15];
    const float* mlp_w1          = (const float*)d_in[16];
    const float* mlp_b1          = (const float*)d_in[17];
    const float* mlp_w2          = (const float*)d_in[18];
    const float* mlp_b2          = (const float*)d_in[19];
    float* slots = (float*)d_out;

    (void)in_sizes; (void)n_in; (void)out_size;

    cudaFuncSetAttribute(k_mma_kv, cudaFuncAttributeMaxDynamicSharedMemorySize, SMEM_SZ);
    cudaFuncSetAttribute(k_gru, cudaFuncAttributeMaxDynamicSharedMemorySize, GRU_SMEM);

    k_q<<<352, 256>>>(slot_noise, slots_mu, slots_log_sigma,
                      ln_slots_scale, ln_slots_offset, Wq, slots);            // 0
    k_prepall<<<16384 + 512, 256>>>(inputs, ln_in_scale, ln_in_offset, Wk, Wv); // 1
    k_mma_kv<<<dim3(4, (B_ * N_) / 128), 256, SMEM_SZ>>>();                   // 2

    for (int it = 0; it < 3; it++) {
        k_attn_upd<<<dim3(32, 16), 256>>>();                                  // 3 at it=0 (profiled)
        k_gx<<<dim3(32, 3), 256>>>(gru_wi);
        k_gru<<<32, 256, GRU_SMEM>>>(gru_wh, gru_b, slots);
        k_mlpq<<<352, 256>>>(ln_mlp_scale, ln_mlp_offset, mlp_w1, mlp_b1, mlp_w2, mlp_b2,
                             ln_slots_scale, ln_slots_offset, Wq, slots);
    }
}

// round 9
// speedup vs baseline: 1.0171x; 1.0151x over previous
#include <cuda_runtime.h>
#include <cuda_bf16.h>
#include <stdint.h>

#define B_ 32
#define N_ 4096
#define D_ 256
#define S_ 11
#define H_ 256
#define M_ 512

// ---------------- scratch (static device globals; no allocs) ----------------
__device__ __nv_bfloat16 g_ahi[(size_t)B_*N_*D_];
__device__ __nv_bfloat16 g_alo[(size_t)B_*N_*D_];
__device__ __nv_bfloat16 g_wthi[512*256];
__device__ __nv_bfloat16 g_wtlo[512*256];
__device__ float g_kf[(size_t)B_*N_*H_];
__device__ float g_vf[(size_t)B_*N_*H_];
__device__ float g_colsum[B_*S_];
__device__ float g_q[B_*S_*H_];
__device__ float g_updraw[B_*S_*H_];
__device__ float g_gx[B_*S_*3*H_];
__device__ float g_hid[B_*S_*M_];

// ---------------- helpers ----------------
__device__ __forceinline__ uint32_t smem_u32(const void* p) {
    uint32_t a;
    asm("{ .reg .u64 t; cvta.to.shared.u64 t, %1; cvt.u32.u64 %0, t; }" : "=r"(a) : "l"(p));
    return a;
}
__device__ __forceinline__ void ldsm_x4(uint32_t& r0, uint32_t& r1, uint32_t& r2, uint32_t& r3,
                                        uint32_t addr) {
    asm volatile("ldmatrix.sync.aligned.m8n8.x4.shared.b16 {%0,%1,%2,%3}, [%4];"
                 : "=r"(r0), "=r"(r1), "=r"(r2), "=r"(r3) : "r"(addr));
}
__device__ __forceinline__ void mma16816(float* d, const uint32_t* a, const uint32_t* b) {
    asm volatile("mma.sync.aligned.m16n8k16.row.col.f32.bf16.bf16.f32 "
                 "{%0,%1,%2,%3}, {%4,%5,%6,%7}, {%8,%9}, {%0,%1,%2,%3};"
                 : "+f"(d[0]), "+f"(d[1]), "+f"(d[2]), "+f"(d[3])
                 : "r"(a[0]), "r"(a[1]), "r"(a[2]), "r"(a[3]), "r"(b[0]), "r"(b[1]));
}
__device__ __forceinline__ void cp16(uint32_t saddr, const void* g) {
    asm volatile("cp.async.cg.shared.global [%0], [%1], 16;" :: "r"(saddr), "l"(g));
}
__device__ __forceinline__ void cp_commit() { asm volatile("cp.async.commit_group;" ::: "memory"); }
__device__ __forceinline__ void cp_wait1()  { asm volatile("cp.async.wait_group 1;" ::: "memory"); }
__device__ __forceinline__ void cp_wait0()  { asm volatile("cp.async.wait_group 0;" ::: "memory"); }

__device__ __forceinline__ void block_reduce2(float& s, float& q) {
    #pragma unroll
    for (int off = 16; off; off >>= 1) {
        s += __shfl_xor_sync(0xffffffffu, s, off);
        q += __shfl_xor_sync(0xffffffffu, q, off);
    }
    __shared__ float ss[8], sq[8];
    int w = threadIdx.x >> 5, l = threadIdx.x & 31;
    if (l == 0) { ss[w] = s; sq[w] = q; }
    __syncthreads();
    s = 0.f; q = 0.f;
    #pragma unroll
    for (int i = 0; i < 8; i++) { s += ss[i]; q += sq[i]; }
}

// ---------------- 1) k_q: [init slots] + zero accum + LN(slots) + q = LN@Wq*scale ----------------
__global__ void __launch_bounds__(256) k_q(int doinit, const float* __restrict__ noise,
                                           const float* __restrict__ mu, const float* __restrict__ ls,
                                           const float* __restrict__ g, const float* __restrict__ o,
                                           const float* __restrict__ Wq, float* __restrict__ slots)
{
    __shared__ float lns[256];
    int r = blockIdx.x, tid = threadIdx.x;
    float val;
    if (doinit) {
        val = mu[tid] + expf(ls[tid]) * noise[r * 256 + tid];
        slots[r * 256 + tid] = val;
    } else {
        val = slots[r * 256 + tid];
    }
    g_updraw[r * 256 + tid] = 0.f;
    if (tid == 0) g_colsum[r] = 0.f;

    float s_ = val, q_ = val * val;
    block_reduce2(s_, q_);
    float muv = s_ * (1.f / 256.f);
    float var = q_ * (1.f / 256.f) - muv * muv;
    float rs = rsqrtf(var + 1e-5f);
    lns[tid] = (val - muv) * rs * g[tid] + o[tid];
    __syncthreads();

    const float* wp = Wq + tid;
    float a0 = 0.f, a1 = 0.f, a2 = 0.f, a3 = 0.f;
    #pragma unroll 4
    for (int k = 0; k < 256; k += 4) {
        a0 = fmaf(lns[k],     wp[(size_t)k * 256],       a0);
        a1 = fmaf(lns[k + 1], wp[(size_t)(k + 1) * 256], a1);
        a2 = fmaf(lns[k + 2], wp[(size_t)(k + 2) * 256], a2);
        a3 = fmaf(lns[k + 3], wp[(size_t)(k + 3) * 256], a3);
    }
    g_q[r * 256 + tid] = ((a0 + a1) + (a2 + a3)) * 0.0625f;
}

// ---------------- 2) combined input-prep + weight-prep ----------------
__global__ void __launch_bounds__(256) k_prepall(const float* __restrict__ x,
                                                 const float* __restrict__ g,
                                                 const float* __restrict__ o,
                                                 const float* __restrict__ wk,
                                                 const float* __restrict__ wv)
{
    if (blockIdx.x >= 16384) {
        int idx = (blockIdx.x - 16384) * 256 + threadIdx.x;
        int j = idx >> 8;
        int k = idx & 255;
        float w = (j < 256) ? wk[k * 256 + j] : wv[k * 256 + (j - 256)];
        __nv_bfloat16 h = __float2bfloat16_rn(w);
        g_wthi[idx] = h;
        g_wtlo[idx] = __float2bfloat16_rn(w - __bfloat162float(h));
        return;
    }
    int wid = threadIdx.x >> 5, lane = threadIdx.x & 31;
    int row = blockIdx.x * 8 + wid;
    const float4* xp = (const float4*)&x[(size_t)row * 256 + lane * 8];
    float4 a = xp[0], b = xp[1];
    float s = a.x + a.y + a.z + a.w + b.x + b.y + b.z + b.w;
    float q = a.x*a.x + a.y*a.y + a.z*a.z + a.w*a.w
            + b.x*b.x + b.y*b.y + b.z*b.z + b.w*b.w;
    #pragma unroll
    for (int off = 16; off; off >>= 1) {
        s += __shfl_xor_sync(0xffffffffu, s, off);
        q += __shfl_xor_sync(0xffffffffu, q, off);
    }
    float mu = s * (1.f / 256.f);
    float var = q * (1.f / 256.f) - mu * mu;
    float rs = rsqrtf(var + 1e-5f);

    const float4* gp = (const float4*)&g[lane * 8];
    const float4* op = (const float4*)&o[lane * 8];
    float4 g0 = gp[0], g1 = gp[1], o0 = op[0], o1 = op[1];

    float v[8];
    v[0] = (a.x - mu) * rs * g0.x + o0.x;
    v[1] = (a.y - mu) * rs * g0.y + o0.y;
    v[2] = (a.z - mu) * rs * g0.z + o0.z;
    v[3] = (a.w - mu) * rs * g0.w + o0.w;
    v[4] = (b.x - mu) * rs * g1.x + o1.x;
    v[5] = (b.y - mu) * rs * g1.y + o1.y;
    v[6] = (b.z - mu) * rs * g1.z + o1.z;
    v[7] = (b.w - mu) * rs * g1.w + o1.w;

    float hf[8], lf[8];
    #pragma unroll
    for (int i = 0; i < 8; i++) {
        __nv_bfloat16 h = __float2bfloat16_rn(v[i]);
        hf[i] = __bfloat162float(h);
        lf[i] = v[i] - hf[i];
    }
    __nv_bfloat162 h01 = __floats2bfloat162_rn(hf[0], hf[1]);
    __nv_bfloat162 h23 = __floats2bfloat162_rn(hf[2], hf[3]);
    __nv_bfloat162 h45 = __floats2bfloat162_rn(hf[4], hf[5]);
    __nv_bfloat162 h67 = __floats2bfloat162_rn(hf[6], hf[7]);
    __nv_bfloat162 l01 = __floats2bfloat162_rn(lf[0], lf[1]);
    __nv_bfloat162 l23 = __floats2bfloat162_rn(lf[2], lf[3]);
    __nv_bfloat162 l45 = __floats2bfloat162_rn(lf[4], lf[5]);
    __nv_bfloat162 l67 = __floats2bfloat162_rn(lf[6], lf[7]);
    uint4 uh, ul;
    uh.x = *(uint32_t*)&h01; uh.y = *(uint32_t*)&h23; uh.z = *(uint32_t*)&h45; uh.w = *(uint32_t*)&h67;
    ul.x = *(uint32_t*)&l01; ul.y = *(uint32_t*)&l23; ul.z = *(uint32_t*)&l45; ul.w = *(uint32_t*)&l67;
    *(uint4*)&g_ahi[(size_t)row * 256 + lane * 8] = uh;
    *(uint4*)&g_alo[(size_t)row * 256 + lane * 8] = ul;
}

// ---------------- 3) mma.sync split-bf16 GEMM, 256 threads (R5 config) ----------------
#define SM_AH 0
#define SM_AL 16384
#define SM_BH 32768
#define SM_BL 49152
#define STAGE_SZ 65536
#define SMEM_SZ (2 * STAGE_SZ)

__device__ __forceinline__ void mma_fill(uint32_t sb, int st, int rowbase, size_t jb, int kb, int tid) {
    uint32_t so = st * STAGE_SZ;
    #pragma unroll
    for (int i = 0; i < 4; i++) {
        int idx = tid + i * 256;
        int row = idx >> 3, c8 = idx & 7;
        uint32_t bo = row * 128 + c8 * 16;
        uint32_t sw = (bo ^ ((bo >> 3) & 0x70)) + so;
        size_t srcA = (size_t)(rowbase + row) * 256 + kb + c8 * 8;
        size_t srcB = jb + (size_t)row * 256 + kb + c8 * 8;
        cp16(sb + SM_AH + sw, &g_ahi[srcA]);
        cp16(sb + SM_AL + sw, &g_alo[srcA]);
        cp16(sb + SM_BH + sw, &g_wthi[srcB]);
        cp16(sb + SM_BL + sw, &g_wtlo[srcB]);
    }
    cp_commit();
}

__global__ void __launch_bounds__(256, 1) k_mma_kv()
{
    extern __shared__ __align__(1024) uint8_t smem[];
    uint32_t sbase = smem_u32(smem);
    int tid = threadIdx.x;
    int lane = tid & 31;
    int warp = tid >> 5;
    int wm = warp & 3;
    int wn = warp >> 2;

    int half = blockIdx.x >> 1;
    int ntile = blockIdx.x & 1;
    int rowbase = blockIdx.y * 128;
    size_t jb = ((size_t)half * 256 + ntile * 128) * 256;

    float acc[2][8][4];
    #pragma unroll
    for (int mf = 0; mf < 2; mf++)
        #pragma unroll
        for (int nf = 0; nf < 8; nf++)
            #pragma unroll
            for (int r = 0; r < 4; r++) acc[mf][nf][r] = 0.f;

    uint32_t lrow = ((lane >> 3) & 1) * 8 + (lane & 7);
    uint32_t lcol = ((lane >> 4) & 1) * 16;

    mma_fill(sbase, 0, rowbase, jb, 0, tid);
    mma_fill(sbase, 1, rowbase, jb, 64, tid);

    for (int ch = 0; ch < 4; ch++) {
        if (ch < 3) cp_wait1();
        else        cp_wait0();
        __syncthreads();
        uint32_t so = (ch & 1) * STAGE_SZ;

        #pragma unroll
        for (int ks = 0; ks < 4; ks++) {
            uint32_t cb = ks * 32 + lcol;
            uint32_t ah[2][4], al[2][4];
            #pragma unroll
            for (int mf = 0; mf < 2; mf++) {
                uint32_t r = wm * 32 + mf * 16 + lrow;
                uint32_t bo = r * 128 + cb;
                uint32_t sw = (bo ^ ((bo >> 3) & 0x70)) + so;
                ldsm_x4(ah[mf][0], ah[mf][1], ah[mf][2], ah[mf][3], sbase + SM_AH + sw);
                ldsm_x4(al[mf][0], al[mf][1], al[mf][2], al[mf][3], sbase + SM_AL + sw);
            }
            uint32_t bh[8][2], bl[8][2];
            #pragma unroll
            for (int g = 0; g < 4; g++) {
                uint32_t r = wn * 64 + g * 16 + lrow;
                uint32_t bo = r * 128 + cb;
                uint32_t sw = (bo ^ ((bo >> 3) & 0x70)) + so;
                uint32_t t0, t1, t2, t3;
                ldsm_x4(t0, t1, t2, t3, sbase + SM_BH + sw);
                bh[g * 2][0] = t0; bh[g * 2 + 1][0] = t1;
                bh[g * 2][1] = t2; bh[g * 2 + 1][1] = t3;
                ldsm_x4(t0, t1, t2, t3, sbase + SM_BL + sw);
                bl[g * 2][0] = t0; bl[g * 2 + 1][0] = t1;
                bl[g * 2][1] = t2; bl[g * 2 + 1][1] = t3;
            }
            #pragma unroll
            for (int mf = 0; mf < 2; mf++)
                #pragma unroll
                for (int nf = 0; nf < 8; nf++) {
                    mma16816(acc[mf][nf], ah[mf], bh[nf]);
                    mma16816(acc[mf][nf], ah[mf], bl[nf]);
                    mma16816(acc[mf][nf], al[mf], bh[nf]);
                }
        }
        __syncthreads();
        if (ch < 2) mma_fill(sbase, ch & 1, rowbase, jb, (ch + 2) * 64, tid);
    }

    float* outp = (half == 0) ? g_kf : g_vf;
    int r0 = rowbase + wm * 32 + (lane >> 2);
    int c0 = ntile * 128 + wn * 64 + (lane & 3) * 2;
    #pragma unroll
    for (int mf = 0; mf < 2; mf++)
        #pragma unroll
        for (int nf = 0; nf < 8; nf++) {
            float* d = acc[mf][nf];
            size_t base = (size_t)(r0 + mf * 16) * 256 + c0 + nf * 8;
            *(float2*)&outp[base] = make_float2(d[0], d[1]);
            *(float2*)&outp[base + 8 * 256] = make_float2(d[2], d[3]);
        }
}

// ---------------- 4) fused attention (R7 version, measured 187us) ----------------
__global__ void __launch_bounds__(256, 2) k_attn_upd()
{
    __shared__ __align__(16) float qs[11][256];
    __shared__ __align__(16) float ps[2][64][12];
    __shared__ float wcs[8][12];
    int b = blockIdx.x, chunk = blockIdx.y, tid = threadIdx.x;
    int warp = tid >> 5, lane = tid & 31;

    for (int i = tid; i < 11 * 256; i += 256) qs[i >> 8][i & 255] = g_q[b * 2816 + i];

    float U[11], csr[11];
    #pragma unroll
    for (int s = 0; s < 11; s++) { U[s] = 0.f; csr[s] = 0.f; }
    int nb = chunk * 256;

    auto phaseA = [&](int base, int buf) {
        #pragma unroll 1
        for (int rr = 0; rr < 8; rr += 2) {
            int nl = base + warp * 8 + rr;
            const float4* k0 = (const float4*)&g_kf[((size_t)(b * 4096 + nb + nl)) * 256];
            const float4* k1 = (const float4*)&g_kf[((size_t)(b * 4096 + nb + nl + 1)) * 256];
            float acc[2][11];
            #pragma unroll
            for (int s = 0; s < 11; s++) { acc[0][s] = 0.f; acc[1][s] = 0.f; }
            #pragma unroll
            for (int i = 0; i < 2; i++) {
                float4 ka = k0[i * 32 + lane];
                float4 kb = k1[i * 32 + lane];
                #pragma unroll
                for (int s = 0; s < 11; s++) {
                    float4 qv = *(const float4*)&qs[s][(i * 32 + lane) * 4];
                    acc[0][s] += ka.x * qv.x + ka.y * qv.y + ka.z * qv.z + ka.w * qv.w;
                    acc[1][s] += kb.x * qv.x + kb.y * qv.y + kb.z * qv.z + kb.w * qv.w;
                }
            }
            #pragma unroll
            for (int off = 16; off; off >>= 1) {
                #pragma unroll
                for (int s = 0; s < 11; s++) {
                    acc[0][s] += __shfl_xor_sync(0xffffffffu, acc[0][s], off);
                    acc[1][s] += __shfl_xor_sync(0xffffffffu, acc[1][s], off);
                }
            }
            #pragma unroll
            for (int r2 = 0; r2 < 2; r2++) {
                float m = acc[r2][0];
                #pragma unroll
                for (int s = 1; s < 11; s++) m = fmaxf(m, acc[r2][s]);
                float e[11], sum = 0.f;
                #pragma unroll
                for (int s = 0; s < 11; s++) { e[s] = expf(acc[r2][s] - m); sum += e[s]; }
                float inv = 1.f / sum;
                #pragma unroll
                for (int s = 0; s < 11; s++) {
                    float p = e[s] * inv + 1e-8f;
                    csr[s] += p;
                    if (lane == 0) ps[buf][warp * 8 + rr + r2][s] = p;
                }
            }
        }
    };

    __syncthreads();
    phaseA(0, 0);
    for (int sub = 0; sub < 4; sub++) {
        __syncthreads();
        const float* vp = &g_vf[((size_t)(b * 4096 + nb + sub * 64)) * 256 + tid];
        const float(*pp)[12] = ps[sub & 1];
        #pragma unroll 8
        for (int n = 0; n < 64; n++) {
            float v = vp[(size_t)n * 256];
            const float4* p4 = (const float4*)&pp[n][0];
            float4 A0 = p4[0], A1 = p4[1], A2 = p4[2];
            U[0] += A0.x * v; U[1] += A0.y * v; U[2]  += A0.z * v; U[3] += A0.w * v;
            U[4] += A1.x * v; U[5] += A1.y * v; U[6]  += A1.z * v; U[7] += A1.w * v;
            U[8] += A2.x * v; U[9] += A2.y * v; U[10] += A2.z * v;
        }
        if (sub < 3) phaseA((sub + 1) * 64, (sub + 1) & 1);
    }

    float* up = &g_updraw[((size_t)b * 11) * 256 + tid];
    #pragma unroll
    for (int s = 0; s < 11; s++) atomicAdd(&up[s * 256], U[s]);

    if (lane == 0) {
        #pragma unroll
        for (int s = 0; s < 11; s++) wcs[warp][s] = csr[s];
    }
    __syncthreads();
    if (tid < 11) {
        float c = 0.f;
        #pragma unroll
        for (int w = 0; w < 8; w++) c += wcs[w][tid];
        atomicAdd(&g_colsum[b * 11 + tid], c);
    }
}

// ---------------- 5) gx = (U / colsum) @ gru_wi ----------------
__global__ void __launch_bounds__(256) k_gx(const float* __restrict__ wi)
{
    __shared__ __align__(16) float ins[256 * 12];
    __shared__ float sinv[11];
    int b = blockIdx.x, jt = blockIdx.y, tid = threadIdx.x;
    if (tid < 11) sinv[tid] = 1.f / g_colsum[b * 11 + tid];
    __syncthreads();
    for (int i = tid; i < 11 * 256; i += 256) {
        int s = i >> 8, k = i & 255;
        ins[k * 12 + s] = g_updraw[((size_t)b * 11 + s) * 256 + k] * sinv[s];
    }
    __syncthreads();

    int j = jt * 256 + tid;
    float acc[11];
    #pragma unroll
    for (int s = 0; s < 11; s++) acc[s] = 0.f;
    const float* wp = wi + j;
    #pragma unroll 2
    for (int k = 0; k < 256; k++) {
        float w = wp[(size_t)k * 768];
        const float4* s4 = (const float4*)&ins[k * 12];
        float4 A0 = s4[0], A1 = s4[1], A2 = s4[2];
        acc[0] += A0.x * w; acc[1] += A0.y * w; acc[2]  += A0.z * w; acc[3] += A0.w * w;
        acc[4] += A1.x * w; acc[5] += A1.y * w; acc[6]  += A1.z * w; acc[7] += A1.w * w;
        acc[8] += A2.x * w; acc[9] += A2.y * w; acc[10] += A2.z * w;
    }
    #pragma unroll
    for (int s = 0; s < 11; s++)
        g_gx[((size_t)b * 11 + s) * 768 + j] = acc[s];
}

// ---------------- 6) GRU scan, cp.async smem-staged weights ----------------
#define GRU_SMEM ((512 + 2 * 32 * 512 + 2 * 32 * 256) * 4)

__global__ void __launch_bounds__(256) k_gru(const float* __restrict__ wh,
                                             const float* __restrict__ gb,
                                             float* __restrict__ slots)
{
    extern __shared__ __align__(16) float sm[];
    float* hs = sm;
    float* rh = sm + 256;
    float* swzr = sm + 512;
    float* swa  = sm + 512 + 2 * 32 * 512;
    uint32_t szr_u = smem_u32(swzr);
    uint32_t sa_u  = smem_u32(swa);

    int b = blockIdx.x;
    int tid = threadIdx.x;
    hs[tid] = 0.f;
    float bz = gb[tid], br = gb[256 + tid], ba = gb[512 + tid];
    __syncthreads();

    for (int s = 0; s < 11; s++) {
        const float* gx = &g_gx[((size_t)b * 11 + s) * 768];
        float az0 = gx[tid] + bz, az1 = 0.f;
        float ar0 = gx[256 + tid] + br, ar1 = 0.f;

        {
            #pragma unroll
            for (int i = 0; i < 16; i++) {
                int idx = tid + i * 256;
                int row = idx >> 7, c4 = idx & 127;
                cp16(szr_u + (row * 512 + c4 * 4) * 4, wh + (size_t)row * 768 + c4 * 4);
            }
            cp_commit();
            for (int c = 0; c < 8; c++) {
                if (c < 7) {
                    int st = (c + 1) & 1;
                    int k0 = (c + 1) * 32;
                    #pragma unroll
                    for (int i = 0; i < 16; i++) {
                        int idx = tid + i * 256;
                        int row = idx >> 7, c4 = idx & 127;
                        cp16(szr_u + (st * 32 * 512 + row * 512 + c4 * 4) * 4,
                             wh + (size_t)(k0 + row) * 768 + c4 * 4);
                    }
                    cp_commit();
                    cp_wait1();
                } else {
                    cp_wait0();
                }
                __syncthreads();
                const float* w = swzr + (c & 1) * 32 * 512;
                int kb = c * 32;
                #pragma unroll 4
                for (int kk = 0; kk < 32; kk += 2) {
                    float h0 = hs[kb + kk], h1 = hs[kb + kk + 1];
                    az0 = fmaf(h0, w[kk * 512 + tid], az0);
                    ar0 = fmaf(h0, w[kk * 512 + 256 + tid], ar0);
                    az1 = fmaf(h1, w[(kk + 1) * 512 + tid], az1);
                    ar1 = fmaf(h1, w[(kk + 1) * 512 + 256 + tid], ar1);
                }
                __syncthreads();
            }
        }
        float z = 1.f / (1.f + expf(-(az0 + az1)));
        float r = 1.f / (1.f + expf(-(ar0 + ar1)));
        float hold = hs[tid];
        rh[tid] = r * hold;
        __syncthreads();

        float aa0 = gx[512 + tid] + ba, aa1 = 0.f;
        {
            #pragma unroll
            for (int i = 0; i < 8; i++) {
                int idx = tid + i * 256;
                int row = idx >> 6, c4 = idx & 63;
                cp16(sa_u + (row * 256 + c4 * 4) * 4, wh + (size_t)row * 768 + 512 + c4 * 4);
            }
            cp_commit();
            for (int c = 0; c < 8; c++) {
                if (c < 7) {
                    int st = (c + 1) & 1;
                    int k0 = (c + 1) * 32;
                    #pragma unroll
                    for (int i = 0; i < 8; i++) {
                        int idx = tid + i * 256;
                        int row = idx >> 6, c4 = idx & 63;
                        cp16(sa_u + (st * 32 * 256 + row * 256 + c4 * 4) * 4,
                             wh + (size_t)(k0 + row) * 768 + 512 + c4 * 4);
                    }
                    cp_commit();
                    cp_wait1();
                } else {
                    cp_wait0();
                }
                __syncthreads();
                const float* w = swa + (c & 1) * 32 * 256;
                int kb = c * 32;
                #pragma unroll 4
                for (int kk = 0; kk < 32; kk += 2) {
                    aa0 = fmaf(rh[kb + kk], w[kk * 256 + tid], aa0);
                    aa1 = fmaf(rh[kb + kk + 1], w[(kk + 1) * 256 + tid], aa1);
                }
                __syncthreads();
            }
        }
        float a = tanhf(aa0 + aa1);
        float hn = (1.f - z) * hold + z * a;
        slots[((size_t)b * 11 + s) * 256 + tid] = hn;
        __syncthreads();
        hs[tid] = hn;
        __syncthreads();
    }
}

// ---------------- 7) k_mlp: slots += relu(LN(slots)@w1+b1)@w2 + b2 (R5 version) ----------------
__global__ void __launch_bounds__(256) k_mlp(const float* __restrict__ g, const float* __restrict__ o,
                                             const float* __restrict__ w1, const float* __restrict__ b1,
                                             const float* __restrict__ w2, const float* __restrict__ b2,
                                             float* __restrict__ slots)
{
    __shared__ float lns[256];
    __shared__ float hid[512];
    int r = blockIdx.x, tid = threadIdx.x;
    float val = slots[r * 256 + tid];
    float s_ = val, q_ = val * val;
    block_reduce2(s_, q_);
    float muv = s_ * (1.f / 256.f);
    float var = q_ * (1.f / 256.f) - muv * muv;
    float rs = rsqrtf(var + 1e-5f);
    lns[tid] = (val - muv) * rs * g[tid] + o[tid];
    __syncthreads();

    const float2* wp = (const float2*)&w1[tid * 2];
    float ax0 = 0.f, ay0 = 0.f, ax1 = 0.f, ay1 = 0.f;
    #pragma unroll 4
    for (int k = 0; k < 256; k += 2) {
        float l0 = lns[k], l1 = lns[k + 1];
        float2 w0 = wp[(size_t)k * 256];
        float2 w1v = wp[(size_t)(k + 1) * 256];
        ax0 = fmaf(l0, w0.x, ax0); ay0 = fmaf(l0, w0.y, ay0);
        ax1 = fmaf(l1, w1v.x, ax1); ay1 = fmaf(l1, w1v.y, ay1);
    }
    float2 bb = *(const float2*)&b1[tid * 2];
    hid[tid * 2]     = fmaxf(ax0 + ax1 + bb.x, 0.f);
    hid[tid * 2 + 1] = fmaxf(ay0 + ay1 + bb.y, 0.f);
    __syncthreads();

    const float* w2p = w2 + tid;
    float a0 = 0.f, a1 = 0.f, a2 = 0.f, a3 = 0.f;
    #pragma unroll 4
    for (int k = 0; k < 512; k += 4) {
        a0 = fmaf(hid[k],     w2p[(size_t)k * 256],       a0);
        a1 = fmaf(hid[k + 1], w2p[(size_t)(k + 1) * 256], a1);
        a2 = fmaf(hid[k + 2], w2p[(size_t)(k + 2) * 256], a2);
        a3 = fmaf(hid[k + 3], w2p[(size_t)(k + 3) * 256], a3);
    }
    slots[r * 256 + tid] = val + ((a0 + a1) + (a2 + a3)) + b2[tid];
}

// ---------------- host launch ----------------
extern "C" void kernel_launch(void* const* d_in, const int* in_sizes, int n_in,
                              void* d_out, int out_size)
{
    const float* inputs          = (const float*)d_in[0];
    const float* slot_noise      = (const float*)d_in[1];
    const float* ln_in_scale     = (const float*)d_in[2];
    const float* ln_in_offset    = (const float*)d_in[3];
    const float* ln_slots_scale  = (const float*)d_in[4];
    const float* ln_slots_offset = (const float*)d_in[5];
    const float* ln_mlp_scale    = (const float*)d_in[6];
    const float* ln_mlp_offset   = (const float*)d_in[7];
    const float* slots_mu        = (const float*)d_in[8];
    const float* slots_log_sigma = (const float*)d_in[9];
    const float* Wq              = (const float*)d_in[10];
    const float* Wk              = (const float*)d_in[11];
    const float* Wv              = (const float*)d_in[12];
    const float* gru_wi          = (const float*)d_in[13];
    const float* gru_wh          = (const float*)d_in[14];
    const float* gru_b           = (const float*)d_in[15];
    const float* mlp_w1          = (const float*)d_in[16];
    const float* mlp_b1          = (const float*)d_in[17];
    const float* mlp_w2          = (const float*)d_in[18];
    const float* mlp_b2          = (const float*)d_in[19];
    float* slots = (float*)d_out;

    (void)in_sizes; (void)n_in; (void)out_size;

    cudaFuncSetAttribute(k_mma_kv, cudaFuncAttributeMaxDynamicSharedMemorySize, SMEM_SZ);
    cudaFuncSetAttribute(k_gru, cudaFuncAttributeMaxDynamicSharedMemorySize, GRU_SMEM);

    k_q<<<352, 256>>>(1, slot_noise, slots_mu, slots_log_sigma,
                      ln_slots_scale, ln_slots_offset, Wq, slots);            // 0
    k_prepall<<<16384 + 512, 256>>>(inputs, ln_in_scale, ln_in_offset, Wk, Wv); // 1
    k_mma_kv<<<dim3(4, (B_ * N_) / 128), 256, SMEM_SZ>>>();                   // 2
    // DIAGNOSTIC dummy gru at the profiled launch index. Reads stale-but-
    // deterministic g_gx, writes slots which is fully overwritten by the real
    // k_gru in iter 0 before any consumer reads it.
    k_gru<<<32, 256, GRU_SMEM>>>(gru_wh, gru_b, slots);                       // 3 (profiled)

    for (int it = 0; it < 3; it++) {
        if (it > 0)
            k_q<<<352, 256>>>(0, slot_noise, slots_mu, slots_log_sigma,
                              ln_slots_scale, ln_slots_offset, Wq, slots);
        k_attn_upd<<<dim3(32, 16), 256>>>();
        k_gx<<<dim3(32, 3), 256>>>(gru_wi);
        k_gru<<<32, 256, GRU_SMEM>>>(gru_wh, gru_b, slots);
        k_mlp<<<352, 256>>>(ln_mlp_scale, ln_mlp_offset, mlp_w1, mlp_b1, mlp_w2, mlp_b2, slots);
    }
}

// round 11
// speedup vs baseline: 1.1033x; 1.0848x over previous
#include <cuda_runtime.h>
#include <cuda_bf16.h>
#include <cuda_fp16.h>
#include <stdint.h>

#define B_ 32
#define N_ 4096
#define D_ 256
#define S_ 11
#define H_ 256
#define M_ 512

// ---------------- scratch (static device globals; no allocs) ----------------
__device__ __nv_bfloat16 g_ahi[(size_t)B_*N_*D_];
__device__ __nv_bfloat16 g_alo[(size_t)B_*N_*D_];
__device__ __nv_bfloat16 g_wthi[512*256];
__device__ __nv_bfloat16 g_wtlo[512*256];
__device__ __half g_kf[(size_t)B_*N_*H_];   // fp16 storage (R11)
__device__ __half g_vf[(size_t)B_*N_*H_];   // fp16 storage (R11)
__device__ float g_colsum[B_*S_];
__device__ float g_q[B_*S_*H_];
__device__ float g_updraw[B_*S_*H_];
__device__ float g_gx[B_*S_*3*H_];

// ---------------- helpers ----------------
__device__ __forceinline__ uint32_t smem_u32(const void* p) {
    uint32_t a;
    asm("{ .reg .u64 t; cvta.to.shared.u64 t, %1; cvt.u32.u64 %0, t; }" : "=r"(a) : "l"(p));
    return a;
}
__device__ __forceinline__ void ldsm_x4(uint32_t& r0, uint32_t& r1, uint32_t& r2, uint32_t& r3,
                                        uint32_t addr) {
    asm volatile("ldmatrix.sync.aligned.m8n8.x4.shared.b16 {%0,%1,%2,%3}, [%4];"
                 : "=r"(r0), "=r"(r1), "=r"(r2), "=r"(r3) : "r"(addr));
}
__device__ __forceinline__ void mma16816(float* d, const uint32_t* a, const uint32_t* b) {
    asm volatile("mma.sync.aligned.m16n8k16.row.col.f32.bf16.bf16.f32 "
                 "{%0,%1,%2,%3}, {%4,%5,%6,%7}, {%8,%9}, {%0,%1,%2,%3};"
                 : "+f"(d[0]), "+f"(d[1]), "+f"(d[2]), "+f"(d[3])
                 : "r"(a[0]), "r"(a[1]), "r"(a[2]), "r"(a[3]), "r"(b[0]), "r"(b[1]));
}
__device__ __forceinline__ void cp16(uint32_t saddr, const void* g) {
    asm volatile("cp.async.cg.shared.global [%0], [%1], 16;" :: "r"(saddr), "l"(g));
}
__device__ __forceinline__ void cp_commit() { asm volatile("cp.async.commit_group;" ::: "memory"); }
__device__ __forceinline__ void cp_wait1()  { asm volatile("cp.async.wait_group 1;" ::: "memory"); }
__device__ __forceinline__ void cp_wait0()  { asm volatile("cp.async.wait_group 0;" ::: "memory"); }

__device__ __forceinline__ void block_reduce2(float& s, float& q) {
    #pragma unroll
    for (int off = 16; off; off >>= 1) {
        s += __shfl_xor_sync(0xffffffffu, s, off);
        q += __shfl_xor_sync(0xffffffffu, q, off);
    }
    __shared__ float ss[8], sq[8];
    int w = threadIdx.x >> 5, l = threadIdx.x & 31;
    if (l == 0) { ss[w] = s; sq[w] = q; }
    __syncthreads();
    s = 0.f; q = 0.f;
    #pragma unroll
    for (int i = 0; i < 8; i++) { s += ss[i]; q += sq[i]; }
}

// ---------------- 1) k_q ----------------
__global__ void __launch_bounds__(256) k_q(int doinit, const float* __restrict__ noise,
                                           const float* __restrict__ mu, const float* __restrict__ ls,
                                           const float* __restrict__ g, const float* __restrict__ o,
                                           const float* __restrict__ Wq, float* __restrict__ slots)
{
    __shared__ float lns[256];
    int r = blockIdx.x, tid = threadIdx.x;
    float val;
    if (doinit) {
        val = mu[tid] + expf(ls[tid]) * noise[r * 256 + tid];
        slots[r * 256 + tid] = val;
    } else {
        val = slots[r * 256 + tid];
    }
    g_updraw[r * 256 + tid] = 0.f;
    if (tid == 0) g_colsum[r] = 0.f;

    float s_ = val, q_ = val * val;
    block_reduce2(s_, q_);
    float muv = s_ * (1.f / 256.f);
    float var = q_ * (1.f / 256.f) - muv * muv;
    float rs = rsqrtf(var + 1e-5f);
    lns[tid] = (val - muv) * rs * g[tid] + o[tid];
    __syncthreads();

    const float* wp = Wq + tid;
    float a0 = 0.f, a1 = 0.f, a2 = 0.f, a3 = 0.f;
    #pragma unroll 4
    for (int k = 0; k < 256; k += 4) {
        a0 = fmaf(lns[k],     wp[(size_t)k * 256],       a0);
        a1 = fmaf(lns[k + 1], wp[(size_t)(k + 1) * 256], a1);
        a2 = fmaf(lns[k + 2], wp[(size_t)(k + 2) * 256], a2);
        a3 = fmaf(lns[k + 3], wp[(size_t)(k + 3) * 256], a3);
    }
    g_q[r * 256 + tid] = ((a0 + a1) + (a2 + a3)) * 0.0625f;
}

// ---------------- 2) combined input-prep + weight-prep ----------------
__global__ void __launch_bounds__(256) k_prepall(const float* __restrict__ x,
                                                 const float* __restrict__ g,
                                                 const float* __restrict__ o,
                                                 const float* __restrict__ wk,
                                                 const float* __restrict__ wv)
{
    if (blockIdx.x >= 16384) {
        int idx = (blockIdx.x - 16384) * 256 + threadIdx.x;
        int j = idx >> 8;
        int k = idx & 255;
        float w = (j < 256) ? wk[k * 256 + j] : wv[k * 256 + (j - 256)];
        __nv_bfloat16 h = __float2bfloat16_rn(w);
        g_wthi[idx] = h;
        g_wtlo[idx] = __float2bfloat16_rn(w - __bfloat162float(h));
        return;
    }
    int wid = threadIdx.x >> 5, lane = threadIdx.x & 31;
    int row = blockIdx.x * 8 + wid;
    const float4* xp = (const float4*)&x[(size_t)row * 256 + lane * 8];
    float4 a = xp[0], b = xp[1];
    float s = a.x + a.y + a.z + a.w + b.x + b.y + b.z + b.w;
    float q = a.x*a.x + a.y*a.y + a.z*a.z + a.w*a.w
            + b.x*b.x + b.y*b.y + b.z*b.z + b.w*b.w;
    #pragma unroll
    for (int off = 16; off; off >>= 1) {
        s += __shfl_xor_sync(0xffffffffu, s, off);
        q += __shfl_xor_sync(0xffffffffu, q, off);
    }
    float mu = s * (1.f / 256.f);
    float var = q * (1.f / 256.f) - mu * mu;
    float rs = rsqrtf(var + 1e-5f);

    const float4* gp = (const float4*)&g[lane * 8];
    const float4* op = (const float4*)&o[lane * 8];
    float4 g0 = gp[0], g1 = gp[1], o0 = op[0], o1 = op[1];

    float v[8];
    v[0] = (a.x - mu) * rs * g0.x + o0.x;
    v[1] = (a.y - mu) * rs * g0.y + o0.y;
    v[2] = (a.z - mu) * rs * g0.z + o0.z;
    v[3] = (a.w - mu) * rs * g0.w + o0.w;
    v[4] = (b.x - mu) * rs * g1.x + o1.x;
    v[5] = (b.y - mu) * rs * g1.y + o1.y;
    v[6] = (b.z - mu) * rs * g1.z + o1.z;
    v[7] = (b.w - mu) * rs * g1.w + o1.w;

    float hf[8], lf[8];
    #pragma unroll
    for (int i = 0; i < 8; i++) {
        __nv_bfloat16 h = __float2bfloat16_rn(v[i]);
        hf[i] = __bfloat162float(h);
        lf[i] = v[i] - hf[i];
    }
    __nv_bfloat162 h01 = __floats2bfloat162_rn(hf[0], hf[1]);
    __nv_bfloat162 h23 = __floats2bfloat162_rn(hf[2], hf[3]);
    __nv_bfloat162 h45 = __floats2bfloat162_rn(hf[4], hf[5]);
    __nv_bfloat162 h67 = __floats2bfloat162_rn(hf[6], hf[7]);
    __nv_bfloat162 l01 = __floats2bfloat162_rn(lf[0], lf[1]);
    __nv_bfloat162 l23 = __floats2bfloat162_rn(lf[2], lf[3]);
    __nv_bfloat162 l45 = __floats2bfloat162_rn(lf[4], lf[5]);
    __nv_bfloat162 l67 = __floats2bfloat162_rn(lf[6], lf[7]);
    uint4 uh, ul;
    uh.x = *(uint32_t*)&h01; uh.y = *(uint32_t*)&h23; uh.z = *(uint32_t*)&h45; uh.w = *(uint32_t*)&h67;
    ul.x = *(uint32_t*)&l01; ul.y = *(uint32_t*)&l23; ul.z = *(uint32_t*)&l45; ul.w = *(uint32_t*)&l67;
    *(uint4*)&g_ahi[(size_t)row * 256 + lane * 8] = uh;
    *(uint4*)&g_alo[(size_t)row * 256 + lane * 8] = ul;
}

// ---------------- 3) mma.sync split-bf16 GEMM, 256 threads, fp16 epilogue ----------------
#define SM_AH 0
#define SM_AL 16384
#define SM_BH 32768
#define SM_BL 49152
#define STAGE_SZ 65536
#define SMEM_SZ (2 * STAGE_SZ)

__device__ __forceinline__ void mma_fill(uint32_t sb, int st, int rowbase, size_t jb, int kb, int tid) {
    uint32_t so = st * STAGE_SZ;
    #pragma unroll
    for (int i = 0; i < 4; i++) {
        int idx = tid + i * 256;
        int row = idx >> 3, c8 = idx & 7;
        uint32_t bo = row * 128 + c8 * 16;
        uint32_t sw = (bo ^ ((bo >> 3) & 0x70)) + so;
        size_t srcA = (size_t)(rowbase + row) * 256 + kb + c8 * 8;
        size_t srcB = jb + (size_t)row * 256 + kb + c8 * 8;
        cp16(sb + SM_AH + sw, &g_ahi[srcA]);
        cp16(sb + SM_AL + sw, &g_alo[srcA]);
        cp16(sb + SM_BH + sw, &g_wthi[srcB]);
        cp16(sb + SM_BL + sw, &g_wtlo[srcB]);
    }
    cp_commit();
}

__global__ void __launch_bounds__(256, 1) k_mma_kv()
{
    extern __shared__ __align__(1024) uint8_t smem[];
    uint32_t sbase = smem_u32(smem);
    int tid = threadIdx.x;
    int lane = tid & 31;
    int warp = tid >> 5;
    int wm = warp & 3;
    int wn = warp >> 2;

    int half = blockIdx.x >> 1;
    int ntile = blockIdx.x & 1;
    int rowbase = blockIdx.y * 128;
    size_t jb = ((size_t)half * 256 + ntile * 128) * 256;

    float acc[2][8][4];
    #pragma unroll
    for (int mf = 0; mf < 2; mf++)
        #pragma unroll
        for (int nf = 0; nf < 8; nf++)
            #pragma unroll
            for (int r = 0; r < 4; r++) acc[mf][nf][r] = 0.f;

    uint32_t lrow = ((lane >> 3) & 1) * 8 + (lane & 7);
    uint32_t lcol = ((lane >> 4) & 1) * 16;

    mma_fill(sbase, 0, rowbase, jb, 0, tid);
    mma_fill(sbase, 1, rowbase, jb, 64, tid);

    for (int ch = 0; ch < 4; ch++) {
        if (ch < 3) cp_wait1();
        else        cp_wait0();
        __syncthreads();
        uint32_t so = (ch & 1) * STAGE_SZ;

        #pragma unroll
        for (int ks = 0; ks < 4; ks++) {
            uint32_t cb = ks * 32 + lcol;
            uint32_t ah[2][4], al[2][4];
            #pragma unroll
            for (int mf = 0; mf < 2; mf++) {
                uint32_t r = wm * 32 + mf * 16 + lrow;
                uint32_t bo = r * 128 + cb;
                uint32_t sw = (bo ^ ((bo >> 3) & 0x70)) + so;
                ldsm_x4(ah[mf][0], ah[mf][1], ah[mf][2], ah[mf][3], sbase + SM_AH + sw);
                ldsm_x4(al[mf][0], al[mf][1], al[mf][2], al[mf][3], sbase + SM_AL + sw);
            }
            uint32_t bh[8][2], bl[8][2];
            #pragma unroll
            for (int g = 0; g < 4; g++) {
                uint32_t r = wn * 64 + g * 16 + lrow;
                uint32_t bo = r * 128 + cb;
                uint32_t sw = (bo ^ ((bo >> 3) & 0x70)) + so;
                uint32_t t0, t1, t2, t3;
                ldsm_x4(t0, t1, t2, t3, sbase + SM_BH + sw);
                bh[g * 2][0] = t0; bh[g * 2 + 1][0] = t1;
                bh[g * 2][1] = t2; bh[g * 2 + 1][1] = t3;
                ldsm_x4(t0, t1, t2, t3, sbase + SM_BL + sw);
                bl[g * 2][0] = t0; bl[g * 2 + 1][0] = t1;
                bl[g * 2][1] = t2; bl[g * 2 + 1][1] = t3;
            }
            #pragma unroll
            for (int mf = 0; mf < 2; mf++)
                #pragma unroll
                for (int nf = 0; nf < 8; nf++) {
                    mma16816(acc[mf][nf], ah[mf], bh[nf]);
                    mma16816(acc[mf][nf], ah[mf], bl[nf]);
                    mma16816(acc[mf][nf], al[mf], bh[nf]);
                }
        }
        __syncthreads();
        if (ch < 2) mma_fill(sbase, ch & 1, rowbase, jb, (ch + 2) * 64, tid);
    }

    __half* outp = (half == 0) ? g_kf : g_vf;
    int r0 = rowbase + wm * 32 + (lane >> 2);
    int c0 = ntile * 128 + wn * 64 + (lane & 3) * 2;
    #pragma unroll
    for (int mf = 0; mf < 2; mf++)
        #pragma unroll
        for (int nf = 0; nf < 8; nf++) {
            float* d = acc[mf][nf];
            size_t base = (size_t)(r0 + mf * 16) * 256 + c0 + nf * 8;
            __half2 p01 = __floats2half2_rn(d[0], d[1]);
            __half2 p23 = __floats2half2_rn(d[2], d[3]);
            *(uint32_t*)&outp[base] = *(uint32_t*)&p01;
            *(uint32_t*)&outp[base + 8 * 256] = *(uint32_t*)&p23;
        }
}

// ---------------- 4) fused attention on fp16 kf/vf ----------------
__global__ void __launch_bounds__(256, 2) k_attn_upd()
{
    __shared__ __align__(16) float qs[11][256];
    __shared__ __align__(16) float ps[2][64][12];
    __shared__ float wcs[8][12];
    int b = blockIdx.x, chunk = blockIdx.y, tid = threadIdx.x;
    int warp = tid >> 5, lane = tid & 31;

    for (int i = tid; i < 11 * 256; i += 256) qs[i >> 8][i & 255] = g_q[b * 2816 + i];

    float U[11], csr[11];
    #pragma unroll
    for (int s = 0; s < 11; s++) { U[s] = 0.f; csr[s] = 0.f; }
    int nb = chunk * 256;

    auto phaseA = [&](int base, int buf) {
        #pragma unroll 1
        for (int rr = 0; rr < 8; rr += 2) {
            int nl = base + warp * 8 + rr;
            uint4 ka = ((const uint4*)&g_kf[((size_t)(b * 4096 + nb + nl)) * 256])[lane];
            uint4 kb = ((const uint4*)&g_kf[((size_t)(b * 4096 + nb + nl + 1)) * 256])[lane];
            float kf0[8], kf1[8];
            {
                const __half2* pa = (const __half2*)&ka;
                const __half2* pb = (const __half2*)&kb;
                #pragma unroll
                for (int j = 0; j < 4; j++) {
                    float2 fa = __half22float2(pa[j]);
                    float2 fb = __half22float2(pb[j]);
                    kf0[2 * j] = fa.x; kf0[2 * j + 1] = fa.y;
                    kf1[2 * j] = fb.x; kf1[2 * j + 1] = fb.y;
                }
            }
            float acc[2][11];
            #pragma unroll
            for (int s = 0; s < 11; s++) { acc[0][s] = 0.f; acc[1][s] = 0.f; }
            #pragma unroll
            for (int s = 0; s < 11; s++) {
                float4 q0 = *(const float4*)&qs[s][lane * 8];
                float4 q1 = *(const float4*)&qs[s][lane * 8 + 4];
                acc[0][s] += kf0[0]*q0.x + kf0[1]*q0.y + kf0[2]*q0.z + kf0[3]*q0.w
                           + kf0[4]*q1.x + kf0[5]*q1.y + kf0[6]*q1.z + kf0[7]*q1.w;
                acc[1][s] += kf1[0]*q0.x + kf1[1]*q0.y + kf1[2]*q0.z + kf1[3]*q0.w
                           + kf1[4]*q1.x + kf1[5]*q1.y + kf1[6]*q1.z + kf1[7]*q1.w;
            }
            #pragma unroll
            for (int off = 16; off; off >>= 1) {
                #pragma unroll
                for (int s = 0; s < 11; s++) {
                    acc[0][s] += __shfl_xor_sync(0xffffffffu, acc[0][s], off);
                    acc[1][s] += __shfl_xor_sync(0xffffffffu, acc[1][s], off);
                }
            }
            #pragma unroll
            for (int r2 = 0; r2 < 2; r2++) {
                float m = acc[r2][0];
                #pragma unroll
                for (int s = 1; s < 11; s++) m = fmaxf(m, acc[r2][s]);
                float e[11], sum = 0.f;
                #pragma unroll
                for (int s = 0; s < 11; s++) { e[s] = expf(acc[r2][s] - m); sum += e[s]; }
                float inv = 1.f / sum;
                #pragma unroll
                for (int s = 0; s < 11; s++) {
                    float p = e[s] * inv + 1e-8f;
                    csr[s] += p;
                    if (lane == 0) ps[buf][warp * 8 + rr + r2][s] = p;
                }
            }
        }
    };

    __syncthreads();
    phaseA(0, 0);
    for (int sub = 0; sub < 4; sub++) {
        __syncthreads();
        const __half* vp = &g_vf[((size_t)(b * 4096 + nb + sub * 64)) * 256 + tid];
        const float(*pp)[12] = ps[sub & 1];
        #pragma unroll 8
        for (int n = 0; n < 64; n++) {
            float v = __half2float(vp[(size_t)n * 256]);
            const float4* p4 = (const float4*)&pp[n][0];
            float4 A0 = p4[0], A1 = p4[1], A2 = p4[2];
            U[0] += A0.x * v; U[1] += A0.y * v; U[2]  += A0.z * v; U[3] += A0.w * v;
            U[4] += A1.x * v; U[5] += A1.y * v; U[6]  += A1.z * v; U[7] += A1.w * v;
            U[8] += A2.x * v; U[9] += A2.y * v; U[10] += A2.z * v;
        }
        if (sub < 3) phaseA((sub + 1) * 64, (sub + 1) & 1);
    }

    float* up = &g_updraw[((size_t)b * 11) * 256 + tid];
    #pragma unroll
    for (int s = 0; s < 11; s++) atomicAdd(&up[s * 256], U[s]);

    if (lane == 0) {
        #pragma unroll
        for (int s = 0; s < 11; s++) wcs[warp][s] = csr[s];
    }
    __syncthreads();
    if (tid < 11) {
        float c = 0.f;
        #pragma unroll
        for (int w = 0; w < 8; w++) c += wcs[w][tid];
        atomicAdd(&g_colsum[b * 11 + tid], c);
    }
}

// ---------------- 5) gx = (U / colsum) @ gru_wi ----------------
__global__ void __launch_bounds__(256) k_gx(const float* __restrict__ wi)
{
    __shared__ __align__(16) float ins[256 * 12];
    __shared__ float sinv[11];
    int b = blockIdx.x, jt = blockIdx.y, tid = threadIdx.x;
    if (tid < 11) sinv[tid] = 1.f / g_colsum[b * 11 + tid];
    __syncthreads();
    for (int i = tid; i < 11 * 256; i += 256) {
        int s = i >> 8, k = i & 255;
        ins[k * 12 + s] = g_updraw[((size_t)b * 11 + s) * 256 + k] * sinv[s];
    }
    __syncthreads();

    int j = jt * 256 + tid;
    float acc[11];
    #pragma unroll
    for (int s = 0; s < 11; s++) acc[s] = 0.f;
    const float* wp = wi + j;
    #pragma unroll 2
    for (int k = 0; k < 256; k++) {
        float w = wp[(size_t)k * 768];
        const float4* s4 = (const float4*)&ins[k * 12];
        float4 A0 = s4[0], A1 = s4[1], A2 = s4[2];
        acc[0] += A0.x * w; acc[1] += A0.y * w; acc[2]  += A0.z * w; acc[3] += A0.w * w;
        acc[4] += A1.x * w; acc[5] += A1.y * w; acc[6]  += A1.z * w; acc[7] += A1.w * w;
        acc[8] += A2.x * w; acc[9] += A2.y * w; acc[10] += A2.z * w;
    }
    #pragma unroll
    for (int s = 0; s < 11; s++)
        g_gx[((size_t)b * 11 + s) * 768 + j] = acc[s];
}

// ---------------- 6) GRU scan, 3-stage cp.async pipeline ----------------
#define GRU_SMEM ((512 + 3 * 32 * 512) * 4)

__global__ void __launch_bounds__(256) k_gru(const float* __restrict__ wh,
                                             const float* __restrict__ gb,
                                             float* __restrict__ slots)
{
    extern __shared__ __align__(16) float sm[];
    float* hs = sm;
    float* rh = sm + 256;
    float* wbuf = sm + 512;
    uint32_t wb_u = smem_u32(wbuf);

    int b = blockIdx.x;
    int tid = threadIdx.x;
    hs[tid] = 0.f;
    float bz = gb[tid], br = gb[256 + tid], ba = gb[512 + tid];
    __syncthreads();

    for (int s = 0; s < 11; s++) {
        const float* gx = &g_gx[((size_t)b * 11 + s) * 768];
        float az0 = gx[tid] + bz, az1 = 0.f;
        float ar0 = gx[256 + tid] + br, ar1 = 0.f;

        auto issueZR = [&](int c) {
            uint32_t so = (uint32_t)(c % 3) * 32 * 512 * 4;
            int k0 = c * 32;
            #pragma unroll
            for (int i = 0; i < 16; i++) {
                int idx = tid + i * 256;
                int row = idx >> 7, c4 = idx & 127;
                cp16(wb_u + so + (row * 512 + c4 * 4) * 4,
                     wh + (size_t)(k0 + row) * 768 + c4 * 4);
            }
            cp_commit();
        };
        issueZR(0);
        issueZR(1);
        for (int c = 0; c < 8; c++) {
            if (c < 7) cp_wait1(); else cp_wait0();
            __syncthreads();
            if (c < 6) issueZR(c + 2);
            const float* w = wbuf + (c % 3) * 32 * 512;
            int kb = c * 32;
            #pragma unroll 4
            for (int kk = 0; kk < 32; kk += 2) {
                float h0 = hs[kb + kk], h1 = hs[kb + kk + 1];
                az0 = fmaf(h0, w[kk * 512 + tid], az0);
                ar0 = fmaf(h0, w[kk * 512 + 256 + tid], ar0);
                az1 = fmaf(h1, w[(kk + 1) * 512 + tid], az1);
                ar1 = fmaf(h1, w[(kk + 1) * 512 + 256 + tid], ar1);
            }
        }
        float z = 1.f / (1.f + expf(-(az0 + az1)));
        float r = 1.f / (1.f + expf(-(ar0 + ar1)));
        float hold = hs[tid];
        rh[tid] = r * hold;

        float aa0 = gx[512 + tid] + ba, aa1 = 0.f;
        auto issueA = [&](int c) {
            uint32_t so = (uint32_t)(c % 3) * 32 * 256 * 4;
            int k0 = c * 32;
            #pragma unroll
            for (int i = 0; i < 8; i++) {
                int idx = tid + i * 256;
                int row = idx >> 6, c4 = idx & 63;
                cp16(wb_u + so + (row * 256 + c4 * 4) * 4,
                     wh + (size_t)(k0 + row) * 768 + 512 + c4 * 4);
            }
            cp_commit();
        };
        issueA(0);
        issueA(1);
        for (int c = 0; c < 8; c++) {
            if (c < 7) cp_wait1(); else cp_wait0();
            __syncthreads();
            if (c < 6) issueA(c + 2);
            const float* w = wbuf + (c % 3) * 32 * 256;
            int kb = c * 32;
            #pragma unroll 4
            for (int kk = 0; kk < 32; kk += 2) {
                aa0 = fmaf(rh[kb + kk], w[kk * 256 + tid], aa0);
                aa1 = fmaf(rh[kb + kk + 1], w[(kk + 1) * 256 + tid], aa1);
            }
        }
        float a = tanhf(aa0 + aa1);
        float hn = (1.f - z) * hold + z * a;
        slots[((size_t)b * 11 + s) * 256 + tid] = hn;
        __syncthreads();
        hs[tid] = hn;
        __syncthreads();
    }
}

// ---------------- 7) k_mlp ----------------
__global__ void __launch_bounds__(256) k_mlp(const float* __restrict__ g, const float* __restrict__ o,
                                             const float* __restrict__ w1, const float* __restrict__ b1,
                                             const float* __restrict__ w2, const float* __restrict__ b2,
                                             float* __restrict__ slots)
{
    __shared__ float lns[256];
    __shared__ float hid[512];
    int r = blockIdx.x, tid = threadIdx.x;
    float val = slots[r * 256 + tid];
    float s_ = val, q_ = val * val;
    block_reduce2(s_, q_);
    float muv = s_ * (1.f / 256.f);
    float var = q_ * (1.f / 256.f) - muv * muv;
    float rs = rsqrtf(var + 1e-5f);
    lns[tid] = (val - muv) * rs * g[tid] + o[tid];
    __syncthreads();

    const float2* wp = (const float2*)&w1[tid * 2];
    float ax0 = 0.f, ay0 = 0.f, ax1 = 0.f, ay1 = 0.f;
    #pragma unroll 4
    for (int k = 0; k < 256; k += 2) {
        float l0 = lns[k], l1 = lns[k + 1];
        float2 w0 = wp[(size_t)k * 256];
        float2 w1v = wp[(size_t)(k + 1) * 256];
        ax0 = fmaf(l0, w0.x, ax0); ay0 = fmaf(l0, w0.y, ay0);
        ax1 = fmaf(l1, w1v.x, ax1); ay1 = fmaf(l1, w1v.y, ay1);
    }
    float2 bb = *(const float2*)&b1[tid * 2];
    hid[tid * 2]     = fmaxf(ax0 + ax1 + bb.x, 0.f);
    hid[tid * 2 + 1] = fmaxf(ay0 + ay1 + bb.y, 0.f);
    __syncthreads();

    const float* w2p = w2 + tid;
    float a0 = 0.f, a1 = 0.f, a2 = 0.f, a3 = 0.f;
    #pragma unroll 4
    for (int k = 0; k < 512; k += 4) {
        a0 = fmaf(hid[k],     w2p[(size_t)k * 256],       a0);
        a1 = fmaf(hid[k + 1], w2p[(size_t)(k + 1) * 256], a1);
        a2 = fmaf(hid[k + 2], w2p[(size_t)(k + 2) * 256], a2);
        a3 = fmaf(hid[k + 3], w2p[(size_t)(k + 3) * 256], a3);
    }
    slots[r * 256 + tid] = val + ((a0 + a1) + (a2 + a3)) + b2[tid];
}

// ---------------- host launch ----------------
extern "C" void kernel_launch(void* const* d_in, const int* in_sizes, int n_in,
                              void* d_out, int out_size)
{
    const float* inputs          = (const float*)d_in[0];
    const float* slot_noise      = (const float*)d_in[1];
    const float* ln_in_scale     = (const float*)d_in[2];
    const float* ln_in_offset    = (const float*)d_in[3];
    const float* ln_slots_scale  = (const float*)d_in[4];
    const float* ln_slots_offset = (const float*)d_in[5];
    const float* ln_mlp_scale    = (const float*)d_in[6];
    const float* ln_mlp_offset   = (const float*)d_in[7];
    const float* slots_mu        = (const float*)d_in[8];
    const float* slots_log_sigma = (const float*)d_in[9];
    const float* Wq              = (const float*)d_in[10];
    const float* Wk              = (const float*)d_in[11];
    const float* Wv              = (const float*)d_in[12];
    const float* gru_wi          = (const float*)d_in[13];
    const float* gru_wh          = (const float*)d_in[14];
    const float* gru_b           = (const float*)d_in[15];
    const float* mlp_w1          = (const float*)d_in[16];
    const float* mlp_b1          = (const float*)d_in[17];
    const float* mlp_w2          = (const float*)d_in[18];
    const float* mlp_b2          = (const float*)d_in[19];
    float* slots = (float*)d_out;

    (void)in_sizes; (void)n_in; (void)out_size;

    cudaFuncSetAttribute(k_mma_kv, cudaFuncAttributeMaxDynamicSharedMemorySize, SMEM_SZ);
    cudaFuncSetAttribute(k_gru, cudaFuncAttributeMaxDynamicSharedMemorySize, GRU_SMEM);

    k_q<<<352, 256>>>(1, slot_noise, slots_mu, slots_log_sigma,
                      ln_slots_scale, ln_slots_offset, Wq, slots);            // 0
    k_prepall<<<16384 + 512, 256>>>(inputs, ln_in_scale, ln_in_offset, Wk, Wv); // 1
    k_mma_kv<<<dim3(4, (B_ * N_) / 128), 256, SMEM_SZ>>>();                   // 2

    for (int it = 0; it < 3; it++) {
        if (it > 0)
            k_q<<<352, 256>>>(0, slot_noise, slots_mu, slots_log_sigma,
                              ln_slots_scale, ln_slots_offset, Wq, slots);
        k_attn_upd<<<dim3(32, 16), 256>>>();                                  // 3 at it=0 (profiled)
        k_gx<<<dim3(32, 3), 256>>>(gru_wi);
        k_gru<<<32, 256, GRU_SMEM>>>(gru_wh, gru_b, slots);
        k_mlp<<<352, 256>>>(ln_mlp_scale, ln_mlp_offset, mlp_w1, mlp_b1, mlp_w2, mlp_b2, slots);
    }
}